// round 1
// baseline (speedup 1.0000x reference)
#include <cuda_runtime.h>
#include <math.h>

// Problem constants (fixed shapes from setup_inputs)
#define B_ 2
#define S_ 2048      // N == M == 2048
#define C_ 1024
#define H_ 16
#define D_ 64
#define GM (B_*S_)   // 4096 rows for the projection GEMMs

// Scratch (device globals; no allocation allowed)
__device__ float g_q[B_*H_*S_*D_];   // 16 MB
__device__ float g_k[B_*H_*S_*D_];   // 16 MB
__device__ float g_v[B_*H_*S_*D_];   // 16 MB
__device__ float g_x[B_*S_*C_];      // 16 MB (attention output, [B,N,C])

// ---------------------------------------------------------------------------
// SGEMM: out = A @ W^T (+bias) (+resid), A:[GM,C_], W:[C_,C_] row-major.
// Tile 128x128, BK=16, 256 threads, 8x8 microtile. Both operands are
// K-contiguous, loaded as float4 and stored transposed [k][m] into smem with
// stride 132 (pad 4) so fragment loads are aligned LDS.128.
// headLayout=1 writes [B,H,S,D]; headLayout=0 writes [B,N,C].
// ---------------------------------------------------------------------------
__global__ __launch_bounds__(256, 2)
void sgemm_kernel(const float* __restrict__ A, const float* __restrict__ W,
                  const float* __restrict__ bias, const float* __restrict__ resid,
                  float* __restrict__ out, int headLayout)
{
    __shared__ float As[16][132];
    __shared__ float Bs[16][132];
    const int tid = threadIdx.x;
    const int m0 = blockIdx.y * 128;
    const int n0 = blockIdx.x * 128;
    const int tx = tid & 15;
    const int ty = tid >> 4;

    float acc[8][8];
#pragma unroll
    for (int i = 0; i < 8; i++)
#pragma unroll
        for (int j = 0; j < 8; j++) acc[i][j] = 0.0f;

    for (int k0 = 0; k0 < C_; k0 += 16) {
#pragma unroll
        for (int i = 0; i < 2; i++) {
            int l = tid + i * 256;          // 0..511 float4 slots
            int row = l >> 2;               // 0..127
            int q = l & 3;                  // which float4 in the 16-wide k strip
            float4 va = *reinterpret_cast<const float4*>(&A[(size_t)(m0 + row) * C_ + k0 + q * 4]);
            As[q * 4 + 0][row] = va.x;
            As[q * 4 + 1][row] = va.y;
            As[q * 4 + 2][row] = va.z;
            As[q * 4 + 3][row] = va.w;
            float4 vb = *reinterpret_cast<const float4*>(&W[(size_t)(n0 + row) * C_ + k0 + q * 4]);
            Bs[q * 4 + 0][row] = vb.x;
            Bs[q * 4 + 1][row] = vb.y;
            Bs[q * 4 + 2][row] = vb.z;
            Bs[q * 4 + 3][row] = vb.w;
        }
        __syncthreads();

#pragma unroll
        for (int kk = 0; kk < 16; kk++) {
            float a[8], b[8];
            *reinterpret_cast<float4*>(&a[0]) = *reinterpret_cast<const float4*>(&As[kk][ty * 8]);
            *reinterpret_cast<float4*>(&a[4]) = *reinterpret_cast<const float4*>(&As[kk][ty * 8 + 4]);
            *reinterpret_cast<float4*>(&b[0]) = *reinterpret_cast<const float4*>(&Bs[kk][tx * 8]);
            *reinterpret_cast<float4*>(&b[4]) = *reinterpret_cast<const float4*>(&Bs[kk][tx * 8 + 4]);
#pragma unroll
            for (int i = 0; i < 8; i++)
#pragma unroll
                for (int j = 0; j < 8; j++)
                    acc[i][j] = fmaf(a[i], b[j], acc[i][j]);
        }
        __syncthreads();
    }

#pragma unroll
    for (int i = 0; i < 8; i++) {
        int r = m0 + ty * 8 + i;
        int bb = r >> 11;          // r / 2048
        int s = r & (S_ - 1);
#pragma unroll
        for (int j = 0; j < 8; j++) {
            int c = n0 + tx * 8 + j;
            float v = acc[i][j];
            if (bias)  v += bias[c];
            if (resid) v += resid[(size_t)r * C_ + c];
            if (headLayout) {
                int h = c >> 6;    // c / 64
                int d = c & 63;
                out[(((size_t)(bb * H_ + h)) * S_ + s) * D_ + d] = v;
            } else {
                out[(size_t)r * C_ + c] = v;
            }
        }
    }
}

// ---------------------------------------------------------------------------
// RoPE applied in-place to g_q and g_k ([B,H,S,D] layout).
// out[j]    = x[j]*cos - x[j+32]*sin
// out[j+32] = x[j+32]*cos + x[j]*sin,  angle = pos * base^(-j/32)
// ---------------------------------------------------------------------------
__global__ void rope_kernel(const int* __restrict__ qpos, const int* __restrict__ kpos)
{
    const int per = B_ * H_ * S_ * (D_ / 2);   // 2,097,152
    int idx = blockIdx.x * blockDim.x + threadIdx.x;
    float* buf;
    const int* pos;
    int t = idx;
    if (idx < per) {
        buf = g_q; pos = qpos;
    } else {
        t = idx - per;
        if (t >= per) return;
        buf = g_k; pos = kpos;
    }
    int j = t & 31;
    int s = (t >> 5) & (S_ - 1);
    int h = (t >> 16) & (H_ - 1);
    int bb = t >> 20;

    int p = pos[bb * S_ + s];
    // inv_freq = 10000^(-j/32) = 2^(-(j/32)*log2(10000))
    float invf = exp2f(-(float)j * (13.287712379549449f / 32.0f));
    float ang = (float)p * invf;
    float sn, cs;
    sincosf(ang, &sn, &cs);

    size_t base = ((size_t)(bb * H_ + h) * S_ + s) * D_;
    float x1 = buf[base + j];
    float x2 = buf[base + j + 32];
    buf[base + j]      = x1 * cs - x2 * sn;
    buf[base + j + 32] = x2 * cs + x1 * sn;
}

// ---------------------------------------------------------------------------
// Flash attention (fp32, online softmax). One block per (b,h, 64-row q tile).
// 256 threads, 4x4 microtiles on 64x64 S / O tiles. smem (dynamic, 69632 B):
//   Qs [d][m] 64x68, Ks [d][n] 64x68, Vs [n][dv] 64x68, Ps [n][m] 64x68
// Writes attention output to g_x in [B,N,C] layout (head-interleaved).
// ---------------------------------------------------------------------------
__global__ __launch_bounds__(256)
void flash_kernel()
{
    extern __shared__ float sm[];
    float* Qs = sm;                // [64][68], transposed [d][m]
    float* Ks = sm + 64 * 68;      // [64][68], transposed [d][n]
    float* Vs = Ks + 64 * 68;      // [64][68], natural [n][dv]
    float* Ps = Vs + 64 * 68;      // [64][68], transposed [n][m]

    const int tid = threadIdx.x;
    const int tx = tid & 15;
    const int ty = tid >> 4;
    const int n0 = blockIdx.x * 64;
    const int h = blockIdx.y;
    const int bb = blockIdx.z;

    const float* qb = g_q + (size_t)(bb * H_ + h) * S_ * D_;
    const float* kb = g_k + (size_t)(bb * H_ + h) * S_ * D_;
    const float* vb = g_v + (size_t)(bb * H_ + h) * S_ * D_;

    // Load Q tile transposed [d][m]
#pragma unroll
    for (int i = 0; i < 4; i++) {
        int l = tid + i * 256;      // 0..1023 float4 slots
        int row = l >> 4;           // 0..63
        int q = l & 15;
        float4 v = *reinterpret_cast<const float4*>(&qb[(size_t)(n0 + row) * D_ + q * 4]);
        Qs[(q * 4 + 0) * 68 + row] = v.x;
        Qs[(q * 4 + 1) * 68 + row] = v.y;
        Qs[(q * 4 + 2) * 68 + row] = v.z;
        Qs[(q * 4 + 3) * 68 + row] = v.w;
    }

    float rmax[4], rsum[4], o[4][4];
#pragma unroll
    for (int i = 0; i < 4; i++) {
        rmax[i] = -1e30f;
        rsum[i] = 0.0f;
#pragma unroll
        for (int j = 0; j < 4; j++) o[i][j] = 0.0f;
    }

    for (int kt = 0; kt < S_; kt += 64) {
        // Load K (transposed) and V (natural) tiles
#pragma unroll
        for (int i = 0; i < 4; i++) {
            int l = tid + i * 256;
            int row = l >> 4;
            int q = l & 15;
            float4 v = *reinterpret_cast<const float4*>(&kb[(size_t)(kt + row) * D_ + q * 4]);
            Ks[(q * 4 + 0) * 68 + row] = v.x;
            Ks[(q * 4 + 1) * 68 + row] = v.y;
            Ks[(q * 4 + 2) * 68 + row] = v.z;
            Ks[(q * 4 + 3) * 68 + row] = v.w;
            float4 w = *reinterpret_cast<const float4*>(&vb[(size_t)(kt + row) * D_ + q * 4]);
            *reinterpret_cast<float4*>(&Vs[row * 68 + q * 4]) = w;
        }
        __syncthreads();

        // S = Q K^T * scale
        float s[4][4];
#pragma unroll
        for (int i = 0; i < 4; i++)
#pragma unroll
            for (int j = 0; j < 4; j++) s[i][j] = 0.0f;

#pragma unroll 16
        for (int d = 0; d < 64; d++) {
            float4 a = *reinterpret_cast<const float4*>(&Qs[d * 68 + ty * 4]);
            float4 b4 = *reinterpret_cast<const float4*>(&Ks[d * 68 + tx * 4]);
            float af[4] = {a.x, a.y, a.z, a.w};
            float bf[4] = {b4.x, b4.y, b4.z, b4.w};
#pragma unroll
            for (int i = 0; i < 4; i++)
#pragma unroll
                for (int j = 0; j < 4; j++)
                    s[i][j] = fmaf(af[i], bf[j], s[i][j]);
        }

        // online softmax per row (rows shared across the 16 tx threads)
#pragma unroll
        for (int i = 0; i < 4; i++) {
#pragma unroll
            for (int j = 0; j < 4; j++) s[i][j] *= 0.125f;   // D^-0.5
            float mx = fmaxf(fmaxf(s[i][0], s[i][1]), fmaxf(s[i][2], s[i][3]));
#pragma unroll
            for (int off = 1; off < 16; off <<= 1)
                mx = fmaxf(mx, __shfl_xor_sync(0xffffffffu, mx, off));
            float mnew = fmaxf(rmax[i], mx);
            float corr = __expf(rmax[i] - mnew);
            rmax[i] = mnew;
            float ps = 0.0f;
#pragma unroll
            for (int j = 0; j < 4; j++) {
                float p = __expf(s[i][j] - mnew);
                s[i][j] = p;
                ps += p;
            }
#pragma unroll
            for (int off = 1; off < 16; off <<= 1)
                ps += __shfl_xor_sync(0xffffffffu, ps, off);
            rsum[i] = rsum[i] * corr + ps;
#pragma unroll
            for (int j = 0; j < 4; j++) o[i][j] *= corr;
        }

        // store P transposed [n][m]
#pragma unroll
        for (int j = 0; j < 4; j++)
#pragma unroll
            for (int i = 0; i < 4; i++)
                Ps[(tx * 4 + j) * 68 + ty * 4 + i] = s[i][j];
        __syncthreads();

        // O += P @ V
#pragma unroll 16
        for (int n = 0; n < 64; n++) {
            float4 a = *reinterpret_cast<const float4*>(&Ps[n * 68 + ty * 4]);
            float4 v4 = *reinterpret_cast<const float4*>(&Vs[n * 68 + tx * 4]);
            float af[4] = {a.x, a.y, a.z, a.w};
            float vf[4] = {v4.x, v4.y, v4.z, v4.w};
#pragma unroll
            for (int i = 0; i < 4; i++)
#pragma unroll
                for (int j = 0; j < 4; j++)
                    o[i][j] = fmaf(af[i], vf[j], o[i][j]);
        }
        __syncthreads();
    }

    // write to g_x in [B,N,C] layout
#pragma unroll
    for (int i = 0; i < 4; i++) {
        float inv = 1.0f / rsum[i];
        int grow = n0 + ty * 4 + i;
        float4 r;
        r.x = o[i][0] * inv;
        r.y = o[i][1] * inv;
        r.z = o[i][2] * inv;
        r.w = o[i][3] * inv;
        *reinterpret_cast<float4*>(&g_x[(size_t)(bb * S_ + grow) * C_ + h * D_ + tx * 4]) = r;
    }
}

// ---------------------------------------------------------------------------
extern "C" void kernel_launch(void* const* d_in, const int* in_sizes, int n_in,
                              void* d_out, int out_size)
{
    const float* query = (const float*)d_in[0];
    const float* key   = (const float*)d_in[1];
    const int*   qpos  = (const int*)d_in[2];
    const int*   kpos  = (const int*)d_in[3];
    const float* Wq    = (const float*)d_in[4];
    const float* bq    = (const float*)d_in[5];
    const float* Wk    = (const float*)d_in[6];
    const float* Wv    = (const float*)d_in[7];
    const float* bv    = (const float*)d_in[8];
    const float* Wo    = (const float*)d_in[9];
    const float* bo    = (const float*)d_in[10];
    float* out = (float*)d_out;

    float *pq, *pk, *pv, *px;
    cudaGetSymbolAddress((void**)&pq, g_q);
    cudaGetSymbolAddress((void**)&pk, g_k);
    cudaGetSymbolAddress((void**)&pv, g_v);
    cudaGetSymbolAddress((void**)&px, g_x);

    const int flash_smem = 4 * 64 * 68 * (int)sizeof(float);   // 69632 B
    cudaFuncSetAttribute(flash_kernel, cudaFuncAttributeMaxDynamicSharedMemorySize, flash_smem);

    dim3 gemm_grid(C_ / 128, GM / 128);   // (8, 32)

    // Q/K/V projections into [B,H,S,D] scratch
    sgemm_kernel<<<gemm_grid, 256>>>(query, Wq, bq,      nullptr, pq, 1);
    sgemm_kernel<<<gemm_grid, 256>>>(key,   Wk, nullptr, nullptr, pk, 1);
    sgemm_kernel<<<gemm_grid, 256>>>(key,   Wv, bv,      nullptr, pv, 1);

    // RoPE in place on q and k
    rope_kernel<<<(2 * B_ * H_ * S_ * (D_ / 2)) / 256, 256>>>(qpos, kpos);

    // attention -> g_x [B,N,C]
    flash_kernel<<<dim3(S_ / 64, H_, B_), 256, flash_smem>>>();

    // output projection + bias + residual -> d_out
    sgemm_kernel<<<gemm_grid, 256>>>(px, Wo, bo, query, out, 0);
}

// round 3
// speedup vs baseline: 2.6520x; 2.6520x over previous
#include <cuda_runtime.h>
#include <math.h>
#include <stdint.h>

// Problem constants (fixed shapes from setup_inputs)
#define B_ 2
#define S_ 2048      // N == M == 2048
#define C_ 1024
#define H_ 16
#define D_ 64
#define GM (B_*S_)   // 4096 rows for the projection GEMMs

// Scratch (device globals; no allocation allowed)
__device__ float g_q[B_*H_*S_*D_];   // 16 MB
__device__ float g_k[B_*H_*S_*D_];   // 16 MB
__device__ float g_v[B_*H_*S_*D_];   // 16 MB
__device__ float g_x[B_*S_*C_];      // 16 MB (attention output, [B,N,C])

__device__ __forceinline__ uint32_t f2tf(float x) {
    uint32_t u;
    asm("cvt.rna.tf32.f32 %0, %1;" : "=r"(u) : "f"(x));
    return u;
}

__device__ __forceinline__ void mma_tf32(float* c, const uint32_t* a, const uint32_t* b) {
    asm volatile(
        "mma.sync.aligned.m16n8k8.row.col.f32.tf32.tf32.f32 "
        "{%0,%1,%2,%3}, {%4,%5,%6,%7}, {%8,%9}, {%0,%1,%2,%3};"
        : "+f"(c[0]), "+f"(c[1]), "+f"(c[2]), "+f"(c[3])
        : "r"(a[0]), "r"(a[1]), "r"(a[2]), "r"(a[3]), "r"(b[0]), "r"(b[1]));
}

// ---------------------------------------------------------------------------
// TF32 tensor-core GEMM: out = A @ W^T (+bias) (+resid)
// A:[GM,C_], W:[C_,C_] row-major (W^T => B operand is k-contiguous = col-major
// for mma.row.col). Tile 128x128, BK=32, 8 warps, warp tile 64x32.
// smem stride 36 words -> fragment LDS bank = (4m+lc)%32, conflict-free.
// headLayout=1 writes [B,H,S,D]; headLayout=0 writes [B,N,C].
// ---------------------------------------------------------------------------
__global__ __launch_bounds__(256, 2)
void gemm_tf32(const float* __restrict__ A, const float* __restrict__ W,
               const float* __restrict__ bias, const float* __restrict__ resid,
               float* __restrict__ out, int headLayout)
{
    __shared__ uint32_t As[128][36];
    __shared__ uint32_t Bs[128][36];

    const int tid = threadIdx.x;
    const int lane = tid & 31;
    const int w = tid >> 5;
    const int wm = (w & 1) * 64;        // warp m offset in tile
    const int wn = (w >> 1) * 32;       // warp n offset in tile
    const int lr = lane >> 2;           // group id (0..7)
    const int lc = lane & 3;            // thread in group (0..3)
    const int m0 = blockIdx.y * 128;
    const int n0 = blockIdx.x * 128;

    float acc[4][4][4];
#pragma unroll
    for (int mt = 0; mt < 4; mt++)
#pragma unroll
        for (int nt = 0; nt < 4; nt++)
#pragma unroll
            for (int j = 0; j < 4; j++) acc[mt][nt][j] = 0.0f;

    for (int k0 = 0; k0 < C_; k0 += 32) {
#pragma unroll
        for (int i = 0; i < 4; i++) {
            int l = tid + i * 256;          // 0..1023
            int row = l >> 3;               // 0..127
            int q = l & 7;                  // float4 slot in the 32-wide k strip
            float4 va = *reinterpret_cast<const float4*>(&A[(size_t)(m0 + row) * C_ + k0 + q * 4]);
            uint4 ua = make_uint4(f2tf(va.x), f2tf(va.y), f2tf(va.z), f2tf(va.w));
            *reinterpret_cast<uint4*>(&As[row][q * 4]) = ua;
            float4 vb = *reinterpret_cast<const float4*>(&W[(size_t)(n0 + row) * C_ + k0 + q * 4]);
            uint4 ub = make_uint4(f2tf(vb.x), f2tf(vb.y), f2tf(vb.z), f2tf(vb.w));
            *reinterpret_cast<uint4*>(&Bs[row][q * 4]) = ub;
        }
        __syncthreads();

#pragma unroll
        for (int kk = 0; kk < 4; kk++) {
            const int kb = kk * 8;
            uint32_t af[4][4], bf[4][2];
#pragma unroll
            for (int mt = 0; mt < 4; mt++) {
                int m = wm + mt * 16 + lr;
                af[mt][0] = As[m][kb + lc];
                af[mt][1] = As[m + 8][kb + lc];
                af[mt][2] = As[m][kb + lc + 4];
                af[mt][3] = As[m + 8][kb + lc + 4];
            }
#pragma unroll
            for (int nt = 0; nt < 4; nt++) {
                int n = wn + nt * 8 + lr;
                bf[nt][0] = Bs[n][kb + lc];
                bf[nt][1] = Bs[n][kb + lc + 4];
            }
#pragma unroll
            for (int mt = 0; mt < 4; mt++)
#pragma unroll
                for (int nt = 0; nt < 4; nt++)
                    mma_tf32(acc[mt][nt], af[mt], bf[nt]);
        }
        __syncthreads();
    }

    // Epilogue: D layout c0:(lr, 2lc) c1:(lr, 2lc+1) c2:(lr+8, 2lc) c3:(lr+8, 2lc+1)
#pragma unroll
    for (int mt = 0; mt < 4; mt++) {
#pragma unroll
        for (int half = 0; half < 2; half++) {
            int r = m0 + wm + mt * 16 + lr + half * 8;
            int bb = r >> 11;
            int s = r & (S_ - 1);
#pragma unroll
            for (int nt = 0; nt < 4; nt++) {
#pragma unroll
                for (int jj = 0; jj < 2; jj++) {
                    int c = n0 + wn + nt * 8 + 2 * lc + jj;
                    float v = acc[mt][nt][half * 2 + jj];
                    if (bias)  v += bias[c];
                    if (resid) v += resid[(size_t)r * C_ + c];
                    if (headLayout) {
                        int h = c >> 6;
                        int d = c & 63;
                        out[(((size_t)(bb * H_ + h)) * S_ + s) * D_ + d] = v;
                    } else {
                        out[(size_t)r * C_ + c] = v;
                    }
                }
            }
        }
    }
}

// ---------------------------------------------------------------------------
// RoPE applied in-place to g_q and g_k ([B,H,S,D] layout).
// ---------------------------------------------------------------------------
__global__ void rope_kernel(const int* __restrict__ qpos, const int* __restrict__ kpos)
{
    const int per = B_ * H_ * S_ * (D_ / 2);
    int idx = blockIdx.x * blockDim.x + threadIdx.x;
    float* buf;
    const int* pos;
    int t = idx;
    if (idx < per) {
        buf = g_q; pos = qpos;
    } else {
        t = idx - per;
        if (t >= per) return;
        buf = g_k; pos = kpos;
    }
    int j = t & 31;
    int s = (t >> 5) & (S_ - 1);
    int h = (t >> 16) & (H_ - 1);
    int bb = t >> 20;

    int p = pos[bb * S_ + s];
    float invf = exp2f(-(float)j * (13.287712379549449f / 32.0f));
    float ang = (float)p * invf;
    float sn, cs;
    sincosf(ang, &sn, &cs);

    size_t base = ((size_t)(bb * H_ + h) * S_ + s) * D_;
    float x1 = buf[base + j];
    float x2 = buf[base + j + 32];
    buf[base + j]      = x1 * cs - x2 * sn;
    buf[base + j + 32] = x2 * cs + x1 * sn;
}

// ---------------------------------------------------------------------------
// Flash attention, tf32 tensor-core. One block per (b, h, 128-row q tile).
// 8 warps; warp w owns q rows [w*16, w*16+16). Q fragments live in registers.
// Dynamic smem (71680 B):
//   KQ : K tile [64][72] (Q tile [128][72] lives here during the prologue)
//   Vs : V tile [64][72]
//   Ps : per-warp P staging [16][68] (16 rows x 64 kv-cols, pad 4)
// ---------------------------------------------------------------------------
#define PSTR 68
__global__ __launch_bounds__(256, 1)
void flash_tf32()
{
    extern __shared__ uint32_t sm[];
    uint32_t* KQ = sm;                         // [64][72]; Q spans [128][72]
    uint32_t* Vs = sm + 64 * 72;               // [64][72]
    const int tid = threadIdx.x;
    const int lane = tid & 31;
    const int w = tid >> 5;
    uint32_t* Ps = sm + 128 * 72 + w * 16 * PSTR; // [16][68] per warp
    const int lr = lane >> 2;
    const int lc = lane & 3;

    const int q0 = blockIdx.x * 128;
    const int h = blockIdx.y;
    const int bb = blockIdx.z;

    const float* qb = g_q + (size_t)(bb * H_ + h) * S_ * D_;
    const float* kb = g_k + (size_t)(bb * H_ + h) * S_ * D_;
    const float* vb = g_v + (size_t)(bb * H_ + h) * S_ * D_;

    // ---- Prologue: load Q tile [128][64] into smem (tf32), extract frags ----
#pragma unroll
    for (int i = 0; i < 8; i++) {
        int l = tid + i * 256;       // 0..2047
        int row = l >> 4;            // 0..127
        int q = l & 15;
        float4 v = *reinterpret_cast<const float4*>(&qb[(size_t)(q0 + row) * D_ + q * 4]);
        uint4 u = make_uint4(f2tf(v.x), f2tf(v.y), f2tf(v.z), f2tf(v.w));
        *reinterpret_cast<uint4*>(&KQ[row * 72 + q * 4]) = u;
    }
    __syncthreads();

    uint32_t qa[8][4];
#pragma unroll
    for (int ks = 0; ks < 8; ks++) {
        int m = w * 16 + lr;
        qa[ks][0] = KQ[m * 72 + ks * 8 + lc];
        qa[ks][1] = KQ[(m + 8) * 72 + ks * 8 + lc];
        qa[ks][2] = KQ[m * 72 + ks * 8 + lc + 4];
        qa[ks][3] = KQ[(m + 8) * 72 + ks * 8 + lc + 4];
    }
    __syncthreads();

    float o[8][4];
#pragma unroll
    for (int nt = 0; nt < 8; nt++)
#pragma unroll
        for (int j = 0; j < 4; j++) o[nt][j] = 0.0f;
    float mrA = -1e30f, mrB = -1e30f, lA = 0.0f, lB = 0.0f;

    for (int kt = 0; kt < S_; kt += 64) {
        // ---- Load K and V tiles (tf32) ----
#pragma unroll
        for (int i = 0; i < 8; i++) {
            int l = tid + i * 256;          // 0..2047; first 1024 = K, rest = V
            int row = (l >> 4) & 63;
            int q = l & 15;
            if (l < 1024) {
                float4 v = *reinterpret_cast<const float4*>(&kb[(size_t)(kt + row) * D_ + q * 4]);
                uint4 u = make_uint4(f2tf(v.x), f2tf(v.y), f2tf(v.z), f2tf(v.w));
                *reinterpret_cast<uint4*>(&KQ[row * 72 + q * 4]) = u;
            } else {
                float4 v = *reinterpret_cast<const float4*>(&vb[(size_t)(kt + row) * D_ + q * 4]);
                uint4 u = make_uint4(f2tf(v.x), f2tf(v.y), f2tf(v.z), f2tf(v.w));
                *reinterpret_cast<uint4*>(&Vs[row * 72 + q * 4]) = u;
            }
        }
        __syncthreads();

        // ---- S = Q K^T ----
        float s[8][4];
#pragma unroll
        for (int nt = 0; nt < 8; nt++)
#pragma unroll
            for (int j = 0; j < 4; j++) s[nt][j] = 0.0f;

#pragma unroll
        for (int ks = 0; ks < 8; ks++) {
#pragma unroll
            for (int nt = 0; nt < 8; nt++) {
                uint32_t bf[2];
                bf[0] = KQ[(nt * 8 + lr) * 72 + ks * 8 + lc];
                bf[1] = KQ[(nt * 8 + lr) * 72 + ks * 8 + lc + 4];
                mma_tf32(s[nt], qa[ks], bf);
            }
        }

        // ---- Online softmax (rows: A = lr, B = lr+8; scale = D^-0.5) ----
        float mA = -1e30f, mB = -1e30f;
#pragma unroll
        for (int nt = 0; nt < 8; nt++) {
#pragma unroll
            for (int j = 0; j < 4; j++) s[nt][j] *= 0.125f;
            mA = fmaxf(mA, fmaxf(s[nt][0], s[nt][1]));
            mB = fmaxf(mB, fmaxf(s[nt][2], s[nt][3]));
        }
        mA = fmaxf(mA, __shfl_xor_sync(0xffffffffu, mA, 1));
        mA = fmaxf(mA, __shfl_xor_sync(0xffffffffu, mA, 2));
        mB = fmaxf(mB, __shfl_xor_sync(0xffffffffu, mB, 1));
        mB = fmaxf(mB, __shfl_xor_sync(0xffffffffu, mB, 2));

        float mnA = fmaxf(mrA, mA);
        float mnB = fmaxf(mrB, mB);
        float cA = __expf(mrA - mnA);
        float cB = __expf(mrB - mnB);
        mrA = mnA; mrB = mnB;

        float sumA = 0.0f, sumB = 0.0f;
#pragma unroll
        for (int nt = 0; nt < 8; nt++) {
            float p0 = __expf(s[nt][0] - mnA);
            float p1 = __expf(s[nt][1] - mnA);
            float p2 = __expf(s[nt][2] - mnB);
            float p3 = __expf(s[nt][3] - mnB);
            sumA += p0 + p1;
            sumB += p2 + p3;
            Ps[lr * PSTR + nt * 8 + 2 * lc]           = f2tf(p0);
            Ps[lr * PSTR + nt * 8 + 2 * lc + 1]       = f2tf(p1);
            Ps[(lr + 8) * PSTR + nt * 8 + 2 * lc]     = f2tf(p2);
            Ps[(lr + 8) * PSTR + nt * 8 + 2 * lc + 1] = f2tf(p3);
        }
        sumA += __shfl_xor_sync(0xffffffffu, sumA, 1);
        sumA += __shfl_xor_sync(0xffffffffu, sumA, 2);
        sumB += __shfl_xor_sync(0xffffffffu, sumB, 1);
        sumB += __shfl_xor_sync(0xffffffffu, sumB, 2);
        lA = lA * cA + sumA;
        lB = lB * cB + sumB;
#pragma unroll
        for (int nt = 0; nt < 8; nt++) {
            o[nt][0] *= cA;
            o[nt][1] *= cA;
            o[nt][2] *= cB;
            o[nt][3] *= cB;
        }
        __syncwarp();

        // ---- O += P V ----
#pragma unroll
        for (int ks = 0; ks < 8; ks++) {
            uint32_t pa[4];
            pa[0] = Ps[lr * PSTR + ks * 8 + lc];
            pa[1] = Ps[(lr + 8) * PSTR + ks * 8 + lc];
            pa[2] = Ps[lr * PSTR + ks * 8 + lc + 4];
            pa[3] = Ps[(lr + 8) * PSTR + ks * 8 + lc + 4];
#pragma unroll
            for (int nt = 0; nt < 8; nt++) {
                uint32_t bv[2];
                bv[0] = Vs[(ks * 8 + lc) * 72 + nt * 8 + lr];
                bv[1] = Vs[(ks * 8 + lc + 4) * 72 + nt * 8 + lr];
                mma_tf32(o[nt], pa, bv);
            }
        }
        __syncthreads();   // protect K/V smem before next iteration's loads
    }

    // ---- Write O to g_x [B,N,C] ----
    float iA = 1.0f / lA;
    float iB = 1.0f / lB;
    int rA = q0 + w * 16 + lr;
    int rB = rA + 8;
    size_t baseA = ((size_t)bb * S_ + rA) * C_ + h * D_;
    size_t baseB = ((size_t)bb * S_ + rB) * C_ + h * D_;
#pragma unroll
    for (int nt = 0; nt < 8; nt++) {
        int c = nt * 8 + 2 * lc;
        g_x[baseA + c]     = o[nt][0] * iA;
        g_x[baseA + c + 1] = o[nt][1] * iA;
        g_x[baseB + c]     = o[nt][2] * iB;
        g_x[baseB + c + 1] = o[nt][3] * iB;
    }
}

// ---------------------------------------------------------------------------
extern "C" void kernel_launch(void* const* d_in, const int* in_sizes, int n_in,
                              void* d_out, int out_size)
{
    const float* query = (const float*)d_in[0];
    const float* key   = (const float*)d_in[1];
    const int*   qpos  = (const int*)d_in[2];
    const int*   kpos  = (const int*)d_in[3];
    const float* Wq    = (const float*)d_in[4];
    const float* bq    = (const float*)d_in[5];
    const float* Wk    = (const float*)d_in[6];
    const float* Wv    = (const float*)d_in[7];
    const float* bv    = (const float*)d_in[8];
    const float* Wo    = (const float*)d_in[9];
    const float* bo    = (const float*)d_in[10];
    float* out = (float*)d_out;

    float *pq, *pk, *pv, *px;
    cudaGetSymbolAddress((void**)&pq, g_q);
    cudaGetSymbolAddress((void**)&pk, g_k);
    cudaGetSymbolAddress((void**)&pv, g_v);
    cudaGetSymbolAddress((void**)&px, g_x);

    const int flash_smem = (128 * 72 + 8 * 16 * PSTR) * (int)sizeof(uint32_t); // 71680
    cudaFuncSetAttribute(flash_tf32, cudaFuncAttributeMaxDynamicSharedMemorySize, flash_smem);

    dim3 gemm_grid(C_ / 128, GM / 128);   // (8, 32)

    // Q/K/V projections into [B,H,S,D] scratch
    gemm_tf32<<<gemm_grid, 256>>>(query, Wq, bq,      nullptr, pq, 1);
    gemm_tf32<<<gemm_grid, 256>>>(key,   Wk, nullptr, nullptr, pk, 1);
    gemm_tf32<<<gemm_grid, 256>>>(key,   Wv, bv,      nullptr, pv, 1);

    // RoPE in place on q and k
    rope_kernel<<<(2 * B_ * H_ * S_ * (D_ / 2)) / 256, 256>>>(qpos, kpos);

    // attention -> g_x [B,N,C]
    flash_tf32<<<dim3(S_ / 128, H_, B_), 256, flash_smem>>>();

    // output projection + bias + residual -> d_out
    gemm_tf32<<<gemm_grid, 256>>>(px, Wo, bo, query, out, 0);
}

// round 4
// speedup vs baseline: 4.5237x; 1.7057x over previous
#include <cuda_runtime.h>
#include <cuda_fp16.h>
#include <math.h>
#include <stdint.h>

// Problem constants (fixed shapes from setup_inputs)
#define B_ 2
#define S_ 2048      // N == M == 2048
#define C_ 1024
#define H_ 16
#define D_ 64
#define GM (B_*S_)   // 4096 rows for the projection GEMMs

// Scratch (device globals; no allocation allowed)
__device__ float g_q[B_*H_*S_*D_];   // 16 MB
__device__ float g_k[B_*H_*S_*D_];   // 16 MB
__device__ float g_v[B_*H_*S_*D_];   // 16 MB
__device__ float g_x[B_*S_*C_];      // 16 MB (attention output, [B,N,C])

__device__ __forceinline__ uint32_t f2h2(float lo, float hi) {
    __half2 h = __floats2half2_rn(lo, hi);
    return *reinterpret_cast<uint32_t*>(&h);
}

__device__ __forceinline__ void mma_f16(float* c, const uint32_t* a, const uint32_t* b) {
    asm volatile(
        "mma.sync.aligned.m16n8k16.row.col.f32.f16.f16.f32 "
        "{%0,%1,%2,%3}, {%4,%5,%6,%7}, {%8,%9}, {%0,%1,%2,%3};"
        : "+f"(c[0]), "+f"(c[1]), "+f"(c[2]), "+f"(c[3])
        : "r"(a[0]), "r"(a[1]), "r"(a[2]), "r"(a[3]), "r"(b[0]), "r"(b[1]));
}

// ---------------------------------------------------------------------------
// FP16 tensor-core GEMM: out = A @ W^T (+bias) (+resid)
// A:[GM,C_], W:[C_,C_] row-major. Tile 128x128, BK=32 (2 x k16 steps),
// 8 warps, warp tile 64x32. Double-buffered smem, register prefetch.
// smem rows of 16 half2-words, stride 20 -> frag reads conflict-free
// (bank = (20*lr + 8ks + lc) % 32 covers all 32).
// headLayout=1 writes [B,H,S,D]; headLayout=0 writes [B,N,C].
// ---------------------------------------------------------------------------
#define ASTR 20
__global__ __launch_bounds__(256, 2)
void gemm_f16k(const float* __restrict__ A, const float* __restrict__ W,
               const float* __restrict__ bias, const float* __restrict__ resid,
               float* __restrict__ out, int headLayout)
{
    __shared__ uint32_t As[2][128 * ASTR];
    __shared__ uint32_t Bs[2][128 * ASTR];

    const int tid = threadIdx.x;
    const int lane = tid & 31;
    const int w = tid >> 5;
    const int wm = (w & 1) * 64;
    const int wn = (w >> 1) * 32;
    const int lr = lane >> 2;
    const int lc = lane & 3;
    const int m0 = blockIdx.y * 128;
    const int n0 = blockIdx.x * 128;

    float acc[4][4][4];
#pragma unroll
    for (int mt = 0; mt < 4; mt++)
#pragma unroll
        for (int nt = 0; nt < 4; nt++)
#pragma unroll
            for (int j = 0; j < 4; j++) acc[mt][nt][j] = 0.0f;

    uint2 pa[4], pb[4];

    // prefetch stage k0 into registers (converted to half2 words)
#define LOAD_STAGE(k0)                                                          \
    {                                                                           \
        _Pragma("unroll")                                                       \
        for (int i = 0; i < 4; i++) {                                           \
            int l = tid + i * 256;                                              \
            int row = l >> 3;                                                   \
            int q = l & 7;                                                      \
            float4 va = *reinterpret_cast<const float4*>(                       \
                &A[(size_t)(m0 + row) * C_ + (k0) + q * 4]);                    \
            pa[i] = make_uint2(f2h2(va.x, va.y), f2h2(va.z, va.w));             \
            float4 vb = *reinterpret_cast<const float4*>(                       \
                &W[(size_t)(n0 + row) * C_ + (k0) + q * 4]);                    \
            pb[i] = make_uint2(f2h2(vb.x, vb.y), f2h2(vb.z, vb.w));             \
        }                                                                       \
    }

#define STORE_STAGE(buf)                                                        \
    {                                                                           \
        _Pragma("unroll")                                                       \
        for (int i = 0; i < 4; i++) {                                           \
            int l = tid + i * 256;                                              \
            int row = l >> 3;                                                   \
            int q = l & 7;                                                      \
            *reinterpret_cast<uint2*>(&As[buf][row * ASTR + q * 2]) = pa[i];    \
            *reinterpret_cast<uint2*>(&Bs[buf][row * ASTR + q * 2]) = pb[i];    \
        }                                                                       \
    }

    LOAD_STAGE(0);
    STORE_STAGE(0);
    __syncthreads();

    int cur = 0;
    const int NIT = C_ / 32;   // 32
    for (int it = 0; it < NIT; it++) {
        if (it + 1 < NIT) LOAD_STAGE((it + 1) * 32);

#pragma unroll
        for (int ks = 0; ks < 2; ks++) {
            uint32_t af[4][4], bf[4][2];
#pragma unroll
            for (int mt = 0; mt < 4; mt++) {
                int m = wm + mt * 16 + lr;
                af[mt][0] = As[cur][m * ASTR + ks * 8 + lc];
                af[mt][1] = As[cur][(m + 8) * ASTR + ks * 8 + lc];
                af[mt][2] = As[cur][m * ASTR + ks * 8 + lc + 4];
                af[mt][3] = As[cur][(m + 8) * ASTR + ks * 8 + lc + 4];
            }
#pragma unroll
            for (int nt = 0; nt < 4; nt++) {
                int n = wn + nt * 8 + lr;
                bf[nt][0] = Bs[cur][n * ASTR + ks * 8 + lc];
                bf[nt][1] = Bs[cur][n * ASTR + ks * 8 + lc + 4];
            }
#pragma unroll
            for (int mt = 0; mt < 4; mt++)
#pragma unroll
                for (int nt = 0; nt < 4; nt++)
                    mma_f16(acc[mt][nt], af[mt], bf[nt]);
        }

        if (it + 1 < NIT) STORE_STAGE(cur ^ 1);
        __syncthreads();
        cur ^= 1;
    }

    // Epilogue: D layout c0:(lr, 2lc) c1:(lr, 2lc+1) c2:(lr+8, 2lc) c3:(lr+8, 2lc+1)
#pragma unroll
    for (int mt = 0; mt < 4; mt++) {
#pragma unroll
        for (int half = 0; half < 2; half++) {
            int r = m0 + wm + mt * 16 + lr + half * 8;
            int bb = r >> 11;
            int s = r & (S_ - 1);
#pragma unroll
            for (int nt = 0; nt < 4; nt++) {
#pragma unroll
                for (int jj = 0; jj < 2; jj++) {
                    int c = n0 + wn + nt * 8 + 2 * lc + jj;
                    float v = acc[mt][nt][half * 2 + jj];
                    if (bias)  v += bias[c];
                    if (resid) v += resid[(size_t)r * C_ + c];
                    if (headLayout) {
                        int h = c >> 6;
                        int d = c & 63;
                        out[(((size_t)(bb * H_ + h)) * S_ + s) * D_ + d] = v;
                    } else {
                        out[(size_t)r * C_ + c] = v;
                    }
                }
            }
        }
    }
}

// ---------------------------------------------------------------------------
// RoPE applied in-place to g_q and g_k ([B,H,S,D] layout).
// ---------------------------------------------------------------------------
__global__ void rope_kernel(const int* __restrict__ qpos, const int* __restrict__ kpos)
{
    const int per = B_ * H_ * S_ * (D_ / 2);
    int idx = blockIdx.x * blockDim.x + threadIdx.x;
    float* buf;
    const int* pos;
    int t = idx;
    if (idx < per) {
        buf = g_q; pos = qpos;
    } else {
        t = idx - per;
        if (t >= per) return;
        buf = g_k; pos = kpos;
    }
    int j = t & 31;
    int s = (t >> 5) & (S_ - 1);
    int h = (t >> 16) & (H_ - 1);
    int bb = t >> 20;

    int p = pos[bb * S_ + s];
    float invf = exp2f(-(float)j * (13.287712379549449f / 32.0f));
    float ang = (float)p * invf;
    float sn, cs;
    sincosf(ang, &sn, &cs);

    size_t base = ((size_t)(bb * H_ + h) * S_ + s) * D_;
    float x1 = buf[base + j];
    float x2 = buf[base + j + 32];
    buf[base + j]      = x1 * cs - x2 * sn;
    buf[base + j + 32] = x2 * cs + x1 * sn;
}

// ---------------------------------------------------------------------------
// Flash attention, fp16 tensor-core. One block per (b, h, 128-row q tile).
// 8 warps; warp w owns q rows [w*16, w*16+16). Q fragments in registers.
// Dynamic smem (46080 B), all rows stride 36 half2-words:
//   KQ : K tile [64 kv][32w] (Q tile [128][32w] lives here during prologue)
//   Vs : V tile TRANSPOSED [64 d][32w of kv-pairs]
//   Ps : per-warp P staging [16 q][32w of kv-pairs]
// ---------------------------------------------------------------------------
#define FSTR 36
__global__ __launch_bounds__(256, 2)
void flash_f16()
{
    extern __shared__ uint32_t sm[];
    uint32_t* KQ = sm;                           // Q: [128][36]; K: [64][36]
    uint32_t* Vs = sm + 128 * FSTR;              // [64][36]
    const int tid = threadIdx.x;
    const int lane = tid & 31;
    const int w = tid >> 5;
    uint32_t* Ps = sm + 192 * FSTR + w * 16 * FSTR;
    const int lr = lane >> 2;
    const int lc = lane & 3;

    const int q0 = blockIdx.x * 128;
    const int h = blockIdx.y;
    const int bb = blockIdx.z;

    const float* qb = g_q + (size_t)(bb * H_ + h) * S_ * D_;
    const float* kb = g_k + (size_t)(bb * H_ + h) * S_ * D_;
    const float* vb = g_v + (size_t)(bb * H_ + h) * S_ * D_;

    // ---- Prologue: Q tile [128][64] -> smem (fp16), extract A-frags ----
#pragma unroll
    for (int i = 0; i < 8; i++) {
        int l = tid + i * 256;       // 0..2047 uint2-slots
        int row = l >> 4;            // 0..127
        int q = l & 15;              // 16 uint2 per row (32 words)
        float4 v = *reinterpret_cast<const float4*>(&qb[(size_t)(q0 + row) * D_ + q * 4]);
        uint2 u = make_uint2(f2h2(v.x, v.y), f2h2(v.z, v.w));
        *reinterpret_cast<uint2*>(&KQ[row * FSTR + q * 2]) = u;
    }
    __syncthreads();

    uint32_t qa[4][4];               // 4 k16-steps over D=64
#pragma unroll
    for (int ks = 0; ks < 4; ks++) {
        int m = w * 16 + lr;
        qa[ks][0] = KQ[m * FSTR + ks * 8 + lc];
        qa[ks][1] = KQ[(m + 8) * FSTR + ks * 8 + lc];
        qa[ks][2] = KQ[m * FSTR + ks * 8 + lc + 4];
        qa[ks][3] = KQ[(m + 8) * FSTR + ks * 8 + lc + 4];
    }
    __syncthreads();

    float o[8][4];
#pragma unroll
    for (int nt = 0; nt < 8; nt++)
#pragma unroll
        for (int j = 0; j < 4; j++) o[nt][j] = 0.0f;
    float mrA = -1e30f, mrB = -1e30f, lA = 0.0f, lB = 0.0f;

    for (int kt = 0; kt < S_; kt += 64) {
        // ---- K tile [64][64] -> smem fp16 ----
#pragma unroll
        for (int i = 0; i < 4; i++) {
            int l = tid + i * 256;      // 0..1023 uint2-slots
            int row = l >> 4;           // 0..63
            int q = l & 15;
            float4 v = *reinterpret_cast<const float4*>(&kb[(size_t)(kt + row) * D_ + q * 4]);
            uint2 u = make_uint2(f2h2(v.x, v.y), f2h2(v.z, v.w));
            *reinterpret_cast<uint2*>(&KQ[row * FSTR + q * 2]) = u;
        }
        // ---- V tile transposed: word (d, j) = half2(V[2j][d], V[2j+1][d]) ----
#pragma unroll
        for (int i = 0; i < 8; i++) {
            int l = tid + i * 256;      // 0..2047 half2-words
            int dpart = l & 7;
            int jpart = (l >> 3) & 3;
            int seg = l >> 5;           // 0..63
            int d = (seg & 7) * 8 + dpart;
            int j = (seg >> 3) * 4 + jpart;
            float lo = vb[(size_t)(kt + 2 * j) * D_ + d];
            float hi = vb[(size_t)(kt + 2 * j + 1) * D_ + d];
            Vs[d * FSTR + j] = f2h2(lo, hi);
        }
        __syncthreads();

        // ---- S = Q K^T ----
        float s[8][4];
#pragma unroll
        for (int nt = 0; nt < 8; nt++)
#pragma unroll
            for (int j = 0; j < 4; j++) s[nt][j] = 0.0f;

#pragma unroll
        for (int ks = 0; ks < 4; ks++) {
#pragma unroll
            for (int nt = 0; nt < 8; nt++) {
                uint32_t bf[2];
                bf[0] = KQ[(nt * 8 + lr) * FSTR + ks * 8 + lc];
                bf[1] = KQ[(nt * 8 + lr) * FSTR + ks * 8 + lc + 4];
                mma_f16(s[nt], qa[ks], bf);
            }
        }

        // ---- Online softmax (rows: A = lr, B = lr+8; scale = D^-0.5) ----
        float mA = -1e30f, mB = -1e30f;
#pragma unroll
        for (int nt = 0; nt < 8; nt++) {
#pragma unroll
            for (int j = 0; j < 4; j++) s[nt][j] *= 0.125f;
            mA = fmaxf(mA, fmaxf(s[nt][0], s[nt][1]));
            mB = fmaxf(mB, fmaxf(s[nt][2], s[nt][3]));
        }
        mA = fmaxf(mA, __shfl_xor_sync(0xffffffffu, mA, 1));
        mA = fmaxf(mA, __shfl_xor_sync(0xffffffffu, mA, 2));
        mB = fmaxf(mB, __shfl_xor_sync(0xffffffffu, mB, 1));
        mB = fmaxf(mB, __shfl_xor_sync(0xffffffffu, mB, 2));

        float mnA = fmaxf(mrA, mA);
        float mnB = fmaxf(mrB, mB);
        float cA = __expf(mrA - mnA);
        float cB = __expf(mrB - mnB);
        mrA = mnA; mrB = mnB;

        float sumA = 0.0f, sumB = 0.0f;
#pragma unroll
        for (int nt = 0; nt < 8; nt++) {
            float p0 = __expf(s[nt][0] - mnA);
            float p1 = __expf(s[nt][1] - mnA);
            float p2 = __expf(s[nt][2] - mnB);
            float p3 = __expf(s[nt][3] - mnB);
            sumA += p0 + p1;
            sumB += p2 + p3;
            Ps[lr * FSTR + nt * 4 + lc]       = f2h2(p0, p1);
            Ps[(lr + 8) * FSTR + nt * 4 + lc] = f2h2(p2, p3);
        }
        sumA += __shfl_xor_sync(0xffffffffu, sumA, 1);
        sumA += __shfl_xor_sync(0xffffffffu, sumA, 2);
        sumB += __shfl_xor_sync(0xffffffffu, sumB, 1);
        sumB += __shfl_xor_sync(0xffffffffu, sumB, 2);
        lA = lA * cA + sumA;
        lB = lB * cB + sumB;
#pragma unroll
        for (int nt = 0; nt < 8; nt++) {
            o[nt][0] *= cA;
            o[nt][1] *= cA;
            o[nt][2] *= cB;
            o[nt][3] *= cB;
        }
        __syncwarp();

        // ---- O += P V (A = P [16 q x 64 kv], B = V^T view [kv x d]) ----
#pragma unroll
        for (int ks = 0; ks < 4; ks++) {
            uint32_t pa[4];
            pa[0] = Ps[lr * FSTR + ks * 8 + lc];
            pa[1] = Ps[(lr + 8) * FSTR + ks * 8 + lc];
            pa[2] = Ps[lr * FSTR + ks * 8 + lc + 4];
            pa[3] = Ps[(lr + 8) * FSTR + ks * 8 + lc + 4];
#pragma unroll
            for (int nt = 0; nt < 8; nt++) {
                uint32_t bv[2];
                bv[0] = Vs[(nt * 8 + lr) * FSTR + ks * 8 + lc];
                bv[1] = Vs[(nt * 8 + lr) * FSTR + ks * 8 + lc + 4];
                mma_f16(o[nt], pa, bv);
            }
        }
        __syncthreads();   // protect K/V smem before next iteration's loads
    }

    // ---- Write O to g_x [B,N,C] ----
    float iA = 1.0f / lA;
    float iB = 1.0f / lB;
    int rA = q0 + w * 16 + lr;
    int rB = rA + 8;
    size_t baseA = ((size_t)bb * S_ + rA) * C_ + h * D_;
    size_t baseB = ((size_t)bb * S_ + rB) * C_ + h * D_;
#pragma unroll
    for (int nt = 0; nt < 8; nt++) {
        int c = nt * 8 + 2 * lc;
        g_x[baseA + c]     = o[nt][0] * iA;
        g_x[baseA + c + 1] = o[nt][1] * iA;
        g_x[baseB + c]     = o[nt][2] * iB;
        g_x[baseB + c + 1] = o[nt][3] * iB;
    }
}

// ---------------------------------------------------------------------------
extern "C" void kernel_launch(void* const* d_in, const int* in_sizes, int n_in,
                              void* d_out, int out_size)
{
    const float* query = (const float*)d_in[0];
    const float* key   = (const float*)d_in[1];
    const int*   qpos  = (const int*)d_in[2];
    const int*   kpos  = (const int*)d_in[3];
    const float* Wq    = (const float*)d_in[4];
    const float* bq    = (const float*)d_in[5];
    const float* Wk    = (const float*)d_in[6];
    const float* Wv    = (const float*)d_in[7];
    const float* bv    = (const float*)d_in[8];
    const float* Wo    = (const float*)d_in[9];
    const float* bo    = (const float*)d_in[10];
    float* out = (float*)d_out;

    float *pq, *pk, *pv, *px;
    cudaGetSymbolAddress((void**)&pq, g_q);
    cudaGetSymbolAddress((void**)&pk, g_k);
    cudaGetSymbolAddress((void**)&pv, g_v);
    cudaGetSymbolAddress((void**)&px, g_x);

    const int flash_smem = (192 * FSTR + 8 * 16 * FSTR) * (int)sizeof(uint32_t); // 46080
    cudaFuncSetAttribute(flash_f16, cudaFuncAttributeMaxDynamicSharedMemorySize, flash_smem);

    dim3 gemm_grid(C_ / 128, GM / 128);   // (8, 32)

    // Q/K/V projections into [B,H,S,D] scratch
    gemm_f16k<<<gemm_grid, 256>>>(query, Wq, bq,      nullptr, pq, 1);
    gemm_f16k<<<gemm_grid, 256>>>(key,   Wk, nullptr, nullptr, pk, 1);
    gemm_f16k<<<gemm_grid, 256>>>(key,   Wv, bv,      nullptr, pv, 1);

    // RoPE in place on q and k
    rope_kernel<<<(2 * B_ * H_ * S_ * (D_ / 2)) / 256, 256>>>(qpos, kpos);

    // attention -> g_x [B,N,C]
    flash_f16<<<dim3(S_ / 128, H_, B_), 256, flash_smem>>>();

    // output projection + bias + residual -> d_out
    gemm_f16k<<<gemm_grid, 256>>>(px, Wo, bo, query, out, 0);
}

// round 5
// speedup vs baseline: 6.4555x; 1.4271x over previous
#include <cuda_runtime.h>
#include <cuda_fp16.h>
#include <stdint.h>
#include <math.h>

// Problem constants (fixed shapes from setup_inputs)
#define B_ 2
#define S_ 2048      // N == M == 2048
#define C_ 1024
#define H_ 16
#define D_ 64
#define GM (B_*S_)   // 4096 rows for the projection GEMMs

// fp16 scratch (device globals; no allocation allowed)
__device__ __half g_hA[GM*C_];       // fp16 query  (A operand for Q proj)
__device__ __half g_hK[GM*C_];       // fp16 key    (A operand for K/V proj)
__device__ __half g_hWq[C_*C_];
__device__ __half g_hWk[C_*C_];
__device__ __half g_hWv[C_*C_];
__device__ __half g_hWo[C_*C_];
__device__ __half g_q[B_*H_*S_*D_];  // [B,H,S,D] fp16
__device__ __half g_k[B_*H_*S_*D_];
__device__ __half g_v[B_*H_*S_*D_];
__device__ __half g_x[B_*S_*C_];     // attention output [B,N,C] fp16

__device__ __forceinline__ uint32_t f2h2(float lo, float hi) {
    __half2 h = __floats2half2_rn(lo, hi);
    return *reinterpret_cast<uint32_t*>(&h);
}

__device__ __forceinline__ void mma_f16(float* c, const uint32_t* a, const uint32_t* b) {
    asm volatile(
        "mma.sync.aligned.m16n8k16.row.col.f32.f16.f16.f32 "
        "{%0,%1,%2,%3}, {%4,%5,%6,%7}, {%8,%9}, {%0,%1,%2,%3};"
        : "+f"(c[0]), "+f"(c[1]), "+f"(c[2]), "+f"(c[3])
        : "r"(a[0]), "r"(a[1]), "r"(a[2]), "r"(a[3]), "r"(b[0]), "r"(b[1]));
}

__device__ __forceinline__ void ldsm4(uint32_t* r, uint32_t a) {
    asm volatile("ldmatrix.sync.aligned.m8n8.x4.shared.b16 {%0,%1,%2,%3}, [%4];"
        : "=r"(r[0]), "=r"(r[1]), "=r"(r[2]), "=r"(r[3]) : "r"(a));
}
__device__ __forceinline__ void ldsm4t(uint32_t* r, uint32_t a) {
    asm volatile("ldmatrix.sync.aligned.m8n8.x4.trans.shared.b16 {%0,%1,%2,%3}, [%4];"
        : "=r"(r[0]), "=r"(r[1]), "=r"(r[2]), "=r"(r[3]) : "r"(a));
}
__device__ __forceinline__ void cpa16(uint32_t saddr, const void* g) {
    asm volatile("cp.async.cg.shared.global [%0], [%1], 16;\n" :: "r"(saddr), "l"(g));
}
#define CP_COMMIT() asm volatile("cp.async.commit_group;\n")
#define CP_WAIT1()  asm volatile("cp.async.wait_group 1;\n")
#define CP_WAIT0()  asm volatile("cp.async.wait_group 0;\n")

// ---------------------------------------------------------------------------
// One-shot fp32 -> fp16 conversion of query, key, Wq, Wk, Wv, Wo.
// Each thread converts one float4.
// ---------------------------------------------------------------------------
__global__ void cvt_kernel(const float* __restrict__ q, const float* __restrict__ k,
                           const float* __restrict__ wq, const float* __restrict__ wk,
                           const float* __restrict__ wv, const float* __restrict__ wo)
{
    int i = blockIdx.x * blockDim.x + threadIdx.x;   // float4 index
    const float* src; __half* dst; int off;
    if      (i < 1048576) { src = q;  dst = g_hA;  off = i; }
    else if (i < 2097152) { src = k;  dst = g_hK;  off = i - 1048576; }
    else if (i < 2359296) { src = wq; dst = g_hWq; off = i - 2097152; }
    else if (i < 2621440) { src = wk; dst = g_hWk; off = i - 2359296; }
    else if (i < 2883584) { src = wv; dst = g_hWv; off = i - 2621440; }
    else                  { src = wo; dst = g_hWo; off = i - 2883584; }
    float4 v = reinterpret_cast<const float4*>(src)[off];
    __half2* d2 = reinterpret_cast<__half2*>(dst) + off * 2;
    d2[0] = __floats2half2_rn(v.x, v.y);
    d2[1] = __floats2half2_rn(v.z, v.w);
}

// ---------------------------------------------------------------------------
// FP16 GEMM: out = A @ W^T (+bias) (+resid). A:[rows][1024], W:[n][1024] fp16.
// 128x128 tile, BK=32, 8 warps (64x32 warp tile), 3-stage cp.async pipeline,
// ldmatrix fragment loads. 64B smem rows, swizzle chunk^((row>>1)&3).
// outh != 0 -> fp16 [B,H,S,D] store; else fp32 [r][C] with residual.
// ---------------------------------------------------------------------------
__global__ __launch_bounds__(256, 2)
void gemm_f16(const __half* __restrict__ A, const __half* __restrict__ W,
              const float* __restrict__ bias, const float* __restrict__ resid,
              __half* __restrict__ outh, float* __restrict__ outf)
{
    __shared__ __half sA[3][128 * 32];
    __shared__ __half sB[3][128 * 32];

    const int tid = threadIdx.x;
    const int lane = tid & 31;
    const int w = tid >> 5;
    const int wm = (w & 1) * 64;
    const int wn = (w >> 1) * 32;
    const int lr = lane >> 2;
    const int lc = lane & 3;
    const int m0 = blockIdx.y * 128;
    const int n0 = blockIdx.x * 128;

    const uint32_t sAb = (uint32_t)__cvta_generic_to_shared(&sA[0][0]);
    const uint32_t sBb = (uint32_t)__cvta_generic_to_shared(&sB[0][0]);

    float acc[4][4][4];
#pragma unroll
    for (int mt = 0; mt < 4; mt++)
#pragma unroll
        for (int nt = 0; nt < 4; nt++)
#pragma unroll
            for (int j = 0; j < 4; j++) acc[mt][nt][j] = 0.0f;

#define G_ISSUE(st, k0)                                                        \
    {                                                                          \
        _Pragma("unroll")                                                      \
        for (int i_ = 0; i_ < 2; i_++) {                                       \
            int l = tid + i_ * 256;                                            \
            int row = l >> 2;                                                  \
            int c = l & 3;                                                     \
            int cs = c ^ ((row >> 1) & 3);                                     \
            cpa16(sAb + (st) * 8192 + row * 64 + cs * 16,                      \
                  A + (size_t)(m0 + row) * C_ + (k0) + c * 8);                 \
            cpa16(sBb + (st) * 8192 + row * 64 + cs * 16,                      \
                  W + (size_t)(n0 + row) * C_ + (k0) + c * 8);                 \
        }                                                                      \
        CP_COMMIT();                                                           \
    }

    G_ISSUE(0, 0);
    G_ISSUE(1, 32);

    const int NIT = C_ / 32;   // 32
    for (int it = 0; it < NIT; it++) {
        if (it + 2 < NIT) CP_WAIT1(); else CP_WAIT0();
        __syncthreads();
        if (it + 2 < NIT) { int st = (it + 2) % 3; G_ISSUE(st, (it + 2) * 32); }

        const int cur = it % 3;
        const uint32_t aB = sAb + cur * 8192;
        const uint32_t bB = sBb + cur * 8192;
#pragma unroll
        for (int ks = 0; ks < 2; ks++) {
            uint32_t bf[2][4];
#pragma unroll
            for (int p = 0; p < 2; p++) {
                int rr = wn + p * 16 + (lane & 7) + ((lane >> 4) << 3);
                int cc = 2 * ks + ((lane >> 3) & 1);
                ldsm4(bf[p], bB + rr * 64 + ((cc ^ ((rr >> 1) & 3)) * 16));
            }
#pragma unroll
            for (int mt = 0; mt < 4; mt++) {
                uint32_t af[4];
                int rr = wm + mt * 16 + (lane & 15);
                int cc = 2 * ks + (lane >> 4);
                ldsm4(af, aB + rr * 64 + ((cc ^ ((rr >> 1) & 3)) * 16));
                mma_f16(acc[mt][0], af, &bf[0][0]);
                mma_f16(acc[mt][1], af, &bf[0][2]);
                mma_f16(acc[mt][2], af, &bf[1][0]);
                mma_f16(acc[mt][3], af, &bf[1][2]);
            }
        }
    }
#undef G_ISSUE

    // Epilogue: acc c0:(lr,2lc) c1:(lr,2lc+1) c2:(lr+8,2lc) c3:(lr+8,2lc+1)
#pragma unroll
    for (int mt = 0; mt < 4; mt++) {
#pragma unroll
        for (int half = 0; half < 2; half++) {
            int r = m0 + wm + mt * 16 + lr + half * 8;
            int bb = r >> 11;
            int s = r & (S_ - 1);
#pragma unroll
            for (int nt = 0; nt < 4; nt++) {
                int c = n0 + wn + nt * 8 + 2 * lc;
                float v0 = acc[mt][nt][half * 2 + 0];
                float v1 = acc[mt][nt][half * 2 + 1];
                if (bias) { v0 += bias[c]; v1 += bias[c + 1]; }
                if (outh) {
                    int h = c >> 6;
                    int d = c & 63;
                    *reinterpret_cast<__half2*>(
                        &outh[(((size_t)(bb * H_ + h)) * S_ + s) * D_ + d]) =
                        __floats2half2_rn(v0, v1);
                } else {
                    v0 += resid[(size_t)r * C_ + c];
                    v1 += resid[(size_t)r * C_ + c + 1];
                    outf[(size_t)r * C_ + c]     = v0;
                    outf[(size_t)r * C_ + c + 1] = v1;
                }
            }
        }
    }
}

// ---------------------------------------------------------------------------
// RoPE in place on fp16 g_q / g_k ([B,H,S,D]). Thread = one (b,h,s, j-pair).
// ---------------------------------------------------------------------------
__global__ void rope_kernel(const int* __restrict__ qpos, const int* __restrict__ kpos)
{
    const int per = B_ * H_ * S_ * 16;   // 2^20 (16 half2-pairs per row)
    int idx = blockIdx.x * blockDim.x + threadIdx.x;
    __half* buf;
    const int* pos;
    int t = idx;
    if (idx < per) { buf = g_q; pos = qpos; }
    else           { t = idx - per; buf = g_k; pos = kpos; }

    int jj = t & 15;
    int s  = (t >> 4) & (S_ - 1);
    int h  = (t >> 15) & (H_ - 1);
    int bb = (t >> 19) & 1;

    int p = pos[bb * S_ + s];
    float sn0, cs0, sn1, cs1;
    {
        float j0 = (float)(2 * jj);
        float invf0 = exp2f(-j0 * (13.287712379549449f / 32.0f));
        float invf1 = exp2f(-(j0 + 1.0f) * (13.287712379549449f / 32.0f));
        sincosf((float)p * invf0, &sn0, &cs0);
        sincosf((float)p * invf1, &sn1, &cs1);
    }

    size_t base = ((size_t)(bb * H_ + h) * S_ + s) * D_;
    __half2 a = *reinterpret_cast<__half2*>(&buf[base + 2 * jj]);
    __half2 b = *reinterpret_cast<__half2*>(&buf[base + 32 + 2 * jj]);
    float x1a = __low2float(a), x1b = __high2float(a);
    float x2a = __low2float(b), x2b = __high2float(b);
    *reinterpret_cast<__half2*>(&buf[base + 2 * jj]) =
        __floats2half2_rn(x1a * cs0 - x2a * sn0, x1b * cs1 - x2b * sn1);
    *reinterpret_cast<__half2*>(&buf[base + 32 + 2 * jj]) =
        __floats2half2_rn(x2a * cs0 + x1a * sn0, x2b * cs1 + x1b * sn1);
}

// ---------------------------------------------------------------------------
// Flash attention, fp16 mma + ldmatrix + cp.async. Block = (b,h, 128 q rows).
// 8 warps; warp w owns q rows [w*16, w*16+16). Dynamic smem 64 KB:
//   Q  [128][64]  halves (swizzled 128B rows)      @ 0
//   K  3 stages [64][64]                           @ 8192 halves
//   V  3 stages [64][64]                           @ 20480 halves
// QK accumulator feeds PV A-fragments directly from registers (no P smem).
// ---------------------------------------------------------------------------
__global__ __launch_bounds__(256)
void flash_f16()
{
    extern __shared__ __half fsm[];
    const uint32_t smb = (uint32_t)__cvta_generic_to_shared(fsm);
    const uint32_t qB = smb;                    // bytes
    const uint32_t kB0 = smb + 8192 * 2;
    const uint32_t vB0 = smb + 20480 * 2;

    const int tid = threadIdx.x;
    const int lane = tid & 31;
    const int w = tid >> 5;
    const int lr = lane >> 2;
    const int lc = lane & 3;

    const int q0 = blockIdx.x * 128;
    const int h = blockIdx.y;
    const int bb = blockIdx.z;

    const __half* qb = g_q + (size_t)(bb * H_ + h) * S_ * D_;
    const __half* kb = g_k + (size_t)(bb * H_ + h) * S_ * D_;
    const __half* vb = g_v + (size_t)(bb * H_ + h) * S_ * D_;

#define KV_ISSUE(st, kt)                                                       \
    {                                                                          \
        _Pragma("unroll")                                                      \
        for (int i_ = 0; i_ < 2; i_++) {                                       \
            int l = tid + i_ * 256;                                            \
            int row = l >> 3;                                                  \
            int c = l & 7;                                                     \
            int cs = c ^ (row & 7);                                            \
            cpa16(kB0 + (st) * 8192 + row * 128 + cs * 16,                     \
                  kb + (size_t)((kt) + row) * D_ + c * 8);                     \
            cpa16(vB0 + (st) * 8192 + row * 128 + cs * 16,                     \
                  vb + (size_t)((kt) + row) * D_ + c * 8);                     \
        }                                                                      \
        CP_COMMIT();                                                           \
    }

    // Prologue: G0 = Q tile + KV stage 0; G1 = KV stage 1
#pragma unroll
    for (int i_ = 0; i_ < 4; i_++) {
        int l = tid + i_ * 256;      // 0..1023
        int row = l >> 3;            // 0..127
        int c = l & 7;
        int cs = c ^ (row & 7);
        cpa16(qB + row * 128 + cs * 16, qb + (size_t)(q0 + row) * D_ + c * 8);
    }
    {
        _Pragma("unroll")
        for (int i_ = 0; i_ < 2; i_++) {
            int l = tid + i_ * 256;
            int row = l >> 3;
            int c = l & 7;
            int cs = c ^ (row & 7);
            cpa16(kB0 + row * 128 + cs * 16, kb + (size_t)row * D_ + c * 8);
            cpa16(vB0 + row * 128 + cs * 16, vb + (size_t)row * D_ + c * 8);
        }
        CP_COMMIT();
    }
    KV_ISSUE(1, 64);

    CP_WAIT1();
    __syncthreads();

    // Q A-fragments (registers for whole kernel)
    uint32_t qa[4][4];
#pragma unroll
    for (int ks = 0; ks < 4; ks++) {
        int rr = w * 16 + (lane & 15);
        int cc = 2 * ks + (lane >> 4);
        ldsm4(qa[ks], qB + rr * 128 + ((cc ^ (rr & 7)) * 16));
    }

    float o[8][4];
#pragma unroll
    for (int nt = 0; nt < 8; nt++)
#pragma unroll
        for (int j = 0; j < 4; j++) o[nt][j] = 0.0f;
    float mrA = -1e30f, mrB = -1e30f, lA = 0.0f, lB = 0.0f;

    const int NITER = S_ / 64;    // 32
    for (int i = 0; i < NITER; i++) {
        if (i > 0) {               // stage i readiness (i==0 handled in prologue)
            if (i + 2 < NITER) CP_WAIT1(); else CP_WAIT0();
            __syncthreads();
        }
        if (i + 2 < NITER) { int st = (i + 2) % 3; KV_ISSUE(st, (i + 2) * 64); }

        const uint32_t kT = kB0 + (i % 3) * 8192;
        const uint32_t vT = vB0 + (i % 3) * 8192;

        // ---- S = Q K^T ----
        float s[8][4];
#pragma unroll
        for (int nt = 0; nt < 8; nt++)
#pragma unroll
            for (int j = 0; j < 4; j++) s[nt][j] = 0.0f;

#pragma unroll
        for (int ks = 0; ks < 4; ks++) {
#pragma unroll
            for (int p = 0; p < 4; p++) {
                uint32_t bf[4];
                int rr = p * 16 + (lane & 7) + ((lane >> 4) << 3);
                int cc = 2 * ks + ((lane >> 3) & 1);
                ldsm4(bf, kT + rr * 128 + ((cc ^ (rr & 7)) * 16));
                mma_f16(s[2 * p],     qa[ks], &bf[0]);
                mma_f16(s[2 * p + 1], qa[ks], &bf[2]);
            }
        }

        // ---- Online softmax (rows A = lr, B = lr+8; scale 0.125) ----
        float mA = -1e30f, mB = -1e30f;
#pragma unroll
        for (int nt = 0; nt < 8; nt++) {
#pragma unroll
            for (int j = 0; j < 4; j++) s[nt][j] *= 0.125f;
            mA = fmaxf(mA, fmaxf(s[nt][0], s[nt][1]));
            mB = fmaxf(mB, fmaxf(s[nt][2], s[nt][3]));
        }
        mA = fmaxf(mA, __shfl_xor_sync(0xffffffffu, mA, 1));
        mA = fmaxf(mA, __shfl_xor_sync(0xffffffffu, mA, 2));
        mB = fmaxf(mB, __shfl_xor_sync(0xffffffffu, mB, 1));
        mB = fmaxf(mB, __shfl_xor_sync(0xffffffffu, mB, 2));

        float mnA = fmaxf(mrA, mA);
        float mnB = fmaxf(mrB, mB);
        float cA = __expf(mrA - mnA);
        float cB = __expf(mrB - mnB);
        mrA = mnA; mrB = mnB;

        float sumA = 0.0f, sumB = 0.0f;
#pragma unroll
        for (int nt = 0; nt < 8; nt++) {
            s[nt][0] = __expf(s[nt][0] - mnA);
            s[nt][1] = __expf(s[nt][1] - mnA);
            s[nt][2] = __expf(s[nt][2] - mnB);
            s[nt][3] = __expf(s[nt][3] - mnB);
            sumA += s[nt][0] + s[nt][1];
            sumB += s[nt][2] + s[nt][3];
        }
        sumA += __shfl_xor_sync(0xffffffffu, sumA, 1);
        sumA += __shfl_xor_sync(0xffffffffu, sumA, 2);
        sumB += __shfl_xor_sync(0xffffffffu, sumB, 1);
        sumB += __shfl_xor_sync(0xffffffffu, sumB, 2);
        lA = lA * cA + sumA;
        lB = lB * cB + sumB;
#pragma unroll
        for (int nt = 0; nt < 8; nt++) {
            o[nt][0] *= cA;
            o[nt][1] *= cA;
            o[nt][2] *= cB;
            o[nt][3] *= cB;
        }

        // ---- O += P V : P A-frags come straight from S registers ----
#pragma unroll
        for (int ks = 0; ks < 4; ks++) {
            uint32_t pa[4];
            pa[0] = f2h2(s[2 * ks][0],     s[2 * ks][1]);
            pa[1] = f2h2(s[2 * ks][2],     s[2 * ks][3]);
            pa[2] = f2h2(s[2 * ks + 1][0], s[2 * ks + 1][1]);
            pa[3] = f2h2(s[2 * ks + 1][2], s[2 * ks + 1][3]);
#pragma unroll
            for (int p = 0; p < 4; p++) {
                uint32_t bv[4];
                int rr = ks * 16 + (lane & 7) + (((lane >> 3) & 1) << 3);
                int cc = 2 * p + (lane >> 4);
                ldsm4t(bv, vT + rr * 128 + ((cc ^ (rr & 7)) * 16));
                mma_f16(o[2 * p],     pa, &bv[0]);
                mma_f16(o[2 * p + 1], pa, &bv[2]);
            }
        }
    }
#undef KV_ISSUE

    // ---- Write O to g_x [B,N,C] (fp16) ----
    float iA = 1.0f / lA;
    float iB = 1.0f / lB;
    int rA = q0 + w * 16 + lr;
    int rB = rA + 8;
    size_t baseA = ((size_t)bb * S_ + rA) * C_ + h * D_;
    size_t baseB = ((size_t)bb * S_ + rB) * C_ + h * D_;
#pragma unroll
    for (int nt = 0; nt < 8; nt++) {
        int c = nt * 8 + 2 * lc;
        *reinterpret_cast<__half2*>(&g_x[baseA + c]) =
            __floats2half2_rn(o[nt][0] * iA, o[nt][1] * iA);
        *reinterpret_cast<__half2*>(&g_x[baseB + c]) =
            __floats2half2_rn(o[nt][2] * iB, o[nt][3] * iB);
    }
}

// ---------------------------------------------------------------------------
extern "C" void kernel_launch(void* const* d_in, const int* in_sizes, int n_in,
                              void* d_out, int out_size)
{
    const float* query = (const float*)d_in[0];
    const float* key   = (const float*)d_in[1];
    const int*   qpos  = (const int*)d_in[2];
    const int*   kpos  = (const int*)d_in[3];
    const float* Wq    = (const float*)d_in[4];
    const float* bq    = (const float*)d_in[5];
    const float* Wk    = (const float*)d_in[6];
    const float* Wv    = (const float*)d_in[7];
    const float* bv    = (const float*)d_in[8];
    const float* Wo    = (const float*)d_in[9];
    const float* bo    = (const float*)d_in[10];
    float* out = (float*)d_out;

    __half *hA, *hK, *hWq, *hWk, *hWv, *hWo, *pq, *pk, *pv, *px;
    cudaGetSymbolAddress((void**)&hA,  g_hA);
    cudaGetSymbolAddress((void**)&hK,  g_hK);
    cudaGetSymbolAddress((void**)&hWq, g_hWq);
    cudaGetSymbolAddress((void**)&hWk, g_hWk);
    cudaGetSymbolAddress((void**)&hWv, g_hWv);
    cudaGetSymbolAddress((void**)&hWo, g_hWo);
    cudaGetSymbolAddress((void**)&pq,  g_q);
    cudaGetSymbolAddress((void**)&pk,  g_k);
    cudaGetSymbolAddress((void**)&pv,  g_v);
    cudaGetSymbolAddress((void**)&px,  g_x);

    const int flash_smem = 32768 * 2;   // 64 KB
    cudaFuncSetAttribute(flash_f16, cudaFuncAttributeMaxDynamicSharedMemorySize, flash_smem);

    // 1. fp32 -> fp16 inputs/weights
    cvt_kernel<<<12288, 256>>>(query, key, Wq, Wk, Wv, Wo);

    // 2. Q/K/V projections into [B,H,S,D] fp16 scratch
    dim3 gemm_grid(C_ / 128, GM / 128);   // (8, 32)
    gemm_f16<<<gemm_grid, 256>>>(hA, hWq, bq,      nullptr, pq, nullptr);
    gemm_f16<<<gemm_grid, 256>>>(hK, hWk, nullptr, nullptr, pk, nullptr);
    gemm_f16<<<gemm_grid, 256>>>(hK, hWv, bv,      nullptr, pv, nullptr);

    // 3. RoPE in place on q and k
    rope_kernel<<<(2 * B_ * H_ * S_ * 16) / 256, 256>>>(qpos, kpos);

    // 4. attention -> g_x [B,N,C] fp16
    flash_f16<<<dim3(S_ / 128, H_, B_), 256, flash_smem>>>();

    // 5. output projection + bias + residual -> d_out (fp32)
    gemm_f16<<<gemm_grid, 256>>>(px, hWo, bo, query, nullptr, out);
}

// round 7
// speedup vs baseline: 6.7423x; 1.0444x over previous
#include <cuda_runtime.h>
#include <cuda_fp16.h>
#include <stdint.h>
#include <math.h>

// Problem constants (fixed shapes from setup_inputs)
#define B_ 2
#define S_ 2048      // N == M == 2048
#define C_ 1024
#define H_ 16
#define D_ 64
#define GM (B_*S_)   // 4096 rows for the projection GEMMs

// fp16 scratch (device globals; no allocation allowed)
__device__ __half g_hA[GM*C_];       // fp16 query
__device__ __half g_hK[GM*C_];       // fp16 key
__device__ __half g_hWq[C_*C_];
__device__ __half g_hWk[C_*C_];
__device__ __half g_hWv[C_*C_];
__device__ __half g_hWo[C_*C_];
__device__ __half g_q[B_*H_*S_*D_];  // [B,H,S,D] fp16
__device__ __half g_k[B_*H_*S_*D_];
__device__ __half g_v[B_*H_*S_*D_];
__device__ __half g_x[B_*S_*C_];     // attention output [B,N,C] fp16

__device__ __forceinline__ uint32_t f2h2(float lo, float hi) {
    __half2 h = __floats2half2_rn(lo, hi);
    return *reinterpret_cast<uint32_t*>(&h);
}
__device__ __forceinline__ void mma_f16(float* c, const uint32_t* a, const uint32_t* b) {
    asm volatile(
        "mma.sync.aligned.m16n8k16.row.col.f32.f16.f16.f32 "
        "{%0,%1,%2,%3}, {%4,%5,%6,%7}, {%8,%9}, {%0,%1,%2,%3};"
        : "+f"(c[0]), "+f"(c[1]), "+f"(c[2]), "+f"(c[3])
        : "r"(a[0]), "r"(a[1]), "r"(a[2]), "r"(a[3]), "r"(b[0]), "r"(b[1]));
}
__device__ __forceinline__ void ldsm4(uint32_t* r, uint32_t a) {
    asm volatile("ldmatrix.sync.aligned.m8n8.x4.shared.b16 {%0,%1,%2,%3}, [%4];"
        : "=r"(r[0]), "=r"(r[1]), "=r"(r[2]), "=r"(r[3]) : "r"(a));
}
__device__ __forceinline__ void ldsm4t(uint32_t* r, uint32_t a) {
    asm volatile("ldmatrix.sync.aligned.m8n8.x4.trans.shared.b16 {%0,%1,%2,%3}, [%4];"
        : "=r"(r[0]), "=r"(r[1]), "=r"(r[2]), "=r"(r[3]) : "r"(a));
}
__device__ __forceinline__ void cpa16(uint32_t saddr, const void* g) {
    asm volatile("cp.async.cg.shared.global [%0], [%1], 16;\n" :: "r"(saddr), "l"(g));
}
#define CP_COMMIT() asm volatile("cp.async.commit_group;\n")
#define CP_WAIT2()  asm volatile("cp.async.wait_group 2;\n")
#define CP_WAIT1()  asm volatile("cp.async.wait_group 1;\n")
#define CP_WAIT0()  asm volatile("cp.async.wait_group 0;\n")

// ---------------------------------------------------------------------------
// One-shot fp32 -> fp16 conversion of query, key, Wq, Wk, Wv, Wo.
// ---------------------------------------------------------------------------
__global__ void cvt_kernel(const float* __restrict__ q, const float* __restrict__ k,
                           const float* __restrict__ wq, const float* __restrict__ wk,
                           const float* __restrict__ wv, const float* __restrict__ wo)
{
    int i = blockIdx.x * blockDim.x + threadIdx.x;   // float4 index
    const float* src; __half* dst; int off;
    if      (i < 1048576) { src = q;  dst = g_hA;  off = i; }
    else if (i < 2097152) { src = k;  dst = g_hK;  off = i - 1048576; }
    else if (i < 2359296) { src = wq; dst = g_hWq; off = i - 2097152; }
    else if (i < 2621440) { src = wk; dst = g_hWk; off = i - 2359296; }
    else if (i < 2883584) { src = wv; dst = g_hWv; off = i - 2621440; }
    else                  { src = wo; dst = g_hWo; off = i - 2883584; }
    float4 v = reinterpret_cast<const float4*>(src)[off];
    __half2* d2 = reinterpret_cast<__half2*>(dst) + off * 2;
    d2[0] = __floats2half2_rn(v.x, v.y);
    d2[1] = __floats2half2_rn(v.z, v.w);
}

// ---------------------------------------------------------------------------
// FP16 GEMM body: out = A @ W^T (+bias) (+resid). A:[rows][1024], W:[n][1024].
// 128x128 tile, BK=32, 8 warps (64x32 warp tile), 4-stage cp.async pipeline
// in 64KB dynamic smem, ldmatrix fragment loads.
// 64B smem rows, swizzle chunk^((row>>1)&3).
// outh != 0 -> fp16 [B,H,S,D] store; else fp32 [r][C] + bias + residual.
// ---------------------------------------------------------------------------
__device__ __forceinline__
void gemm_body(const __half* __restrict__ A, const __half* __restrict__ W,
               const float* __restrict__ bias, const float* __restrict__ resid,
               __half* __restrict__ outh, float* __restrict__ outf)
{
    extern __shared__ __half gsm[];
    const uint32_t sAb = (uint32_t)__cvta_generic_to_shared(gsm);            // 4 x 8KB
    const uint32_t sBb = sAb + 32768;                                        // 4 x 8KB

    const int tid = threadIdx.x;
    const int lane = tid & 31;
    const int w = tid >> 5;
    const int wm = (w & 1) * 64;
    const int wn = (w >> 1) * 32;
    const int lr = lane >> 2;
    const int lc = lane & 3;
    const int m0 = blockIdx.y * 128;
    const int n0 = blockIdx.x * 128;

    float acc[4][4][4];
#pragma unroll
    for (int mt = 0; mt < 4; mt++)
#pragma unroll
        for (int nt = 0; nt < 4; nt++)
#pragma unroll
            for (int j = 0; j < 4; j++) acc[mt][nt][j] = 0.0f;

#define G_ISSUE(st, k0)                                                        \
    {                                                                          \
        _Pragma("unroll")                                                      \
        for (int i_ = 0; i_ < 2; i_++) {                                       \
            int l = tid + i_ * 256;                                            \
            int row = l >> 2;                                                  \
            int c = l & 3;                                                     \
            int cs = c ^ ((row >> 1) & 3);                                     \
            cpa16(sAb + (st) * 8192 + row * 64 + cs * 16,                      \
                  A + (size_t)(m0 + row) * C_ + (k0) + c * 8);                 \
            cpa16(sBb + (st) * 8192 + row * 64 + cs * 16,                      \
                  W + (size_t)(n0 + row) * C_ + (k0) + c * 8);                 \
        }                                                                      \
    }

    G_ISSUE(0, 0);   CP_COMMIT();
    G_ISSUE(1, 32);  CP_COMMIT();
    G_ISSUE(2, 64);  CP_COMMIT();

    const int NIT = C_ / 32;   // 32
    for (int it = 0; it < NIT; it++) {
        CP_WAIT2();
        __syncthreads();
        // uniform commit count: empty groups past the end keep wait_group 2 exact
        if (it + 3 < NIT) { int st = (it + 3) & 3; G_ISSUE(st, (it + 3) * 32); }
        CP_COMMIT();

        const int cur = it & 3;
        const uint32_t aB = sAb + cur * 8192;
        const uint32_t bB = sBb + cur * 8192;
#pragma unroll
        for (int ks = 0; ks < 2; ks++) {
            uint32_t bf[2][4];
#pragma unroll
            for (int p = 0; p < 2; p++) {
                int rr = wn + p * 16 + (lane & 7) + ((lane >> 4) << 3);
                int cc = 2 * ks + ((lane >> 3) & 1);
                ldsm4(bf[p], bB + rr * 64 + ((cc ^ ((rr >> 1) & 3)) * 16));
            }
#pragma unroll
            for (int mt = 0; mt < 4; mt++) {
                uint32_t af[4];
                int rr = wm + mt * 16 + (lane & 15);
                int cc = 2 * ks + (lane >> 4);
                ldsm4(af, aB + rr * 64 + ((cc ^ ((rr >> 1) & 3)) * 16));
                mma_f16(acc[mt][0], af, &bf[0][0]);
                mma_f16(acc[mt][1], af, &bf[0][2]);
                mma_f16(acc[mt][2], af, &bf[1][0]);
                mma_f16(acc[mt][3], af, &bf[1][2]);
            }
        }
    }
#undef G_ISSUE

    // Epilogue: acc c0:(lr,2lc) c1:(lr,2lc+1) c2:(lr+8,2lc) c3:(lr+8,2lc+1)
#pragma unroll
    for (int mt = 0; mt < 4; mt++) {
#pragma unroll
        for (int half = 0; half < 2; half++) {
            int r = m0 + wm + mt * 16 + lr + half * 8;
            int bb = r >> 11;
            int s = r & (S_ - 1);
#pragma unroll
            for (int nt = 0; nt < 4; nt++) {
                int c = n0 + wn + nt * 8 + 2 * lc;
                float v0 = acc[mt][nt][half * 2 + 0];
                float v1 = acc[mt][nt][half * 2 + 1];
                if (bias) { v0 += bias[c]; v1 += bias[c + 1]; }
                if (outh) {
                    int h = c >> 6;
                    int d = c & 63;
                    *reinterpret_cast<__half2*>(
                        &outh[(((size_t)(bb * H_ + h)) * S_ + s) * D_ + d]) =
                        __floats2half2_rn(v0, v1);
                } else {
                    v0 += resid[(size_t)r * C_ + c];
                    v1 += resid[(size_t)r * C_ + c + 1];
                    outf[(size_t)r * C_ + c]     = v0;
                    outf[(size_t)r * C_ + c + 1] = v1;
                }
            }
        }
    }
}

// Merged Q/K/V projection: grid.z selects (source, weight, bias, dest).
__global__ __launch_bounds__(256, 2)
void gemm_qkv(const float* __restrict__ bq, const float* __restrict__ bv)
{
    const __half* A; const __half* W; const float* bias; __half* outh;
    if (blockIdx.z == 0)      { A = g_hA; W = g_hWq; bias = bq;      outh = g_q; }
    else if (blockIdx.z == 1) { A = g_hK; W = g_hWk; bias = nullptr; outh = g_k; }
    else                      { A = g_hK; W = g_hWv; bias = bv;      outh = g_v; }
    gemm_body(A, W, bias, nullptr, outh, nullptr);
}

// Output projection: fp32 out + bias + residual.
__global__ __launch_bounds__(256, 2)
void gemm_o(const float* __restrict__ bo, const float* __restrict__ resid,
            float* __restrict__ out)
{
    gemm_body(g_x, g_hWo, bo, resid, nullptr, out);
}

// ---------------------------------------------------------------------------
// RoPE in place on fp16 g_q / g_k ([B,H,S,D]). 4 threads per row; each
// thread loads uint4 (8 halves) at j0=8q and its partner at j0+32.
// ---------------------------------------------------------------------------
__global__ void rope_kernel(const int* __restrict__ qpos, const int* __restrict__ kpos)
{
    int t = blockIdx.x * blockDim.x + threadIdx.x;   // 524288 threads
    int q = t & 3;
    int row = t >> 2;                                // 0..131071
    __half* buf;
    const int* pos;
    int r = row;
    if (row < 65536) { buf = g_q; pos = qpos; }
    else             { r = row - 65536; buf = g_k; pos = kpos; }
    int s  = r & (S_ - 1);
    int bb = r >> 15;

    int p = pos[bb * S_ + s];
    float fp = (float)p;

    size_t base = (size_t)r * D_ + 8 * q;
    uint4 X = *reinterpret_cast<const uint4*>(&buf[base]);
    uint4 Y = *reinterpret_cast<const uint4*>(&buf[base + 32]);
    const __half2* xh = reinterpret_cast<const __half2*>(&X);
    const __half2* yh = reinterpret_cast<const __half2*>(&Y);
    uint4 Xo, Yo;
    __half2* xo = reinterpret_cast<__half2*>(&Xo);
    __half2* yo = reinterpret_cast<__half2*>(&Yo);

#pragma unroll
    for (int i = 0; i < 4; i++) {
        int j0 = 8 * q + 2 * i;
        float invf0 = exp2f(-(float)j0 * (13.287712379549449f / 32.0f));
        float invf1 = exp2f(-(float)(j0 + 1) * (13.287712379549449f / 32.0f));
        float sn0, cs0, sn1, cs1;
        sincosf(fp * invf0, &sn0, &cs0);
        sincosf(fp * invf1, &sn1, &cs1);
        float x1a = __low2float(xh[i]), x1b = __high2float(xh[i]);
        float x2a = __low2float(yh[i]), x2b = __high2float(yh[i]);
        xo[i] = __floats2half2_rn(x1a * cs0 - x2a * sn0, x1b * cs1 - x2b * sn1);
        yo[i] = __floats2half2_rn(x2a * cs0 + x1a * sn0, x2b * cs1 + x1b * sn1);
    }
    *reinterpret_cast<uint4*>(&buf[base])      = Xo;
    *reinterpret_cast<uint4*>(&buf[base + 32]) = Yo;
}

// ---------------------------------------------------------------------------
// Flash attention, fp16 mma + ldmatrix + cp.async (proven R5 version).
// ---------------------------------------------------------------------------
__global__ __launch_bounds__(256)
void flash_f16()
{
    extern __shared__ __half fsm[];
    const uint32_t smb = (uint32_t)__cvta_generic_to_shared(fsm);
    const uint32_t qB = smb;
    const uint32_t kB0 = smb + 8192 * 2;
    const uint32_t vB0 = smb + 20480 * 2;

    const int tid = threadIdx.x;
    const int lane = tid & 31;
    const int w = tid >> 5;
    const int lr = lane >> 2;
    const int lc = lane & 3;

    const int q0 = blockIdx.x * 128;
    const int h = blockIdx.y;
    const int bb = blockIdx.z;

    const __half* qb = g_q + (size_t)(bb * H_ + h) * S_ * D_;
    const __half* kb = g_k + (size_t)(bb * H_ + h) * S_ * D_;
    const __half* vb = g_v + (size_t)(bb * H_ + h) * S_ * D_;

#define KV_ISSUE(st, kt)                                                       \
    {                                                                          \
        _Pragma("unroll")                                                      \
        for (int i_ = 0; i_ < 2; i_++) {                                       \
            int l = tid + i_ * 256;                                            \
            int row = l >> 3;                                                  \
            int c = l & 7;                                                     \
            int cs = c ^ (row & 7);                                            \
            cpa16(kB0 + (st) * 8192 + row * 128 + cs * 16,                     \
                  kb + (size_t)((kt) + row) * D_ + c * 8);                     \
            cpa16(vB0 + (st) * 8192 + row * 128 + cs * 16,                     \
                  vb + (size_t)((kt) + row) * D_ + c * 8);                     \
        }                                                                      \
        CP_COMMIT();                                                           \
    }

#pragma unroll
    for (int i_ = 0; i_ < 4; i_++) {
        int l = tid + i_ * 256;
        int row = l >> 3;
        int c = l & 7;
        int cs = c ^ (row & 7);
        cpa16(qB + row * 128 + cs * 16, qb + (size_t)(q0 + row) * D_ + c * 8);
    }
    {
        _Pragma("unroll")
        for (int i_ = 0; i_ < 2; i_++) {
            int l = tid + i_ * 256;
            int row = l >> 3;
            int c = l & 7;
            int cs = c ^ (row & 7);
            cpa16(kB0 + row * 128 + cs * 16, kb + (size_t)row * D_ + c * 8);
            cpa16(vB0 + row * 128 + cs * 16, vb + (size_t)row * D_ + c * 8);
        }
        CP_COMMIT();
    }
    KV_ISSUE(1, 64);

    CP_WAIT1();
    __syncthreads();

    uint32_t qa[4][4];
#pragma unroll
    for (int ks = 0; ks < 4; ks++) {
        int rr = w * 16 + (lane & 15);
        int cc = 2 * ks + (lane >> 4);
        ldsm4(qa[ks], qB + rr * 128 + ((cc ^ (rr & 7)) * 16));
    }

    float o[8][4];
#pragma unroll
    for (int nt = 0; nt < 8; nt++)
#pragma unroll
        for (int j = 0; j < 4; j++) o[nt][j] = 0.0f;
    float mrA = -1e30f, mrB = -1e30f, lA = 0.0f, lB = 0.0f;

    const int NITER = S_ / 64;    // 32
    for (int i = 0; i < NITER; i++) {
        if (i > 0) {
            if (i + 2 < NITER) CP_WAIT1(); else CP_WAIT0();
            __syncthreads();
        }
        if (i + 2 < NITER) { int st = (i + 2) % 3; KV_ISSUE(st, (i + 2) * 64); }

        const uint32_t kT = kB0 + (i % 3) * 8192;
        const uint32_t vT = vB0 + (i % 3) * 8192;

        float s[8][4];
#pragma unroll
        for (int nt = 0; nt < 8; nt++)
#pragma unroll
            for (int j = 0; j < 4; j++) s[nt][j] = 0.0f;

#pragma unroll
        for (int ks = 0; ks < 4; ks++) {
#pragma unroll
            for (int p = 0; p < 4; p++) {
                uint32_t bf[4];
                int rr = p * 16 + (lane & 7) + ((lane >> 4) << 3);
                int cc = 2 * ks + ((lane >> 3) & 1);
                ldsm4(bf, kT + rr * 128 + ((cc ^ (rr & 7)) * 16));
                mma_f16(s[2 * p],     qa[ks], &bf[0]);
                mma_f16(s[2 * p + 1], qa[ks], &bf[2]);
            }
        }

        float mA = -1e30f, mB = -1e30f;
#pragma unroll
        for (int nt = 0; nt < 8; nt++) {
#pragma unroll
            for (int j = 0; j < 4; j++) s[nt][j] *= 0.125f;
            mA = fmaxf(mA, fmaxf(s[nt][0], s[nt][1]));
            mB = fmaxf(mB, fmaxf(s[nt][2], s[nt][3]));
        }
        mA = fmaxf(mA, __shfl_xor_sync(0xffffffffu, mA, 1));
        mA = fmaxf(mA, __shfl_xor_sync(0xffffffffu, mA, 2));
        mB = fmaxf(mB, __shfl_xor_sync(0xffffffffu, mB, 1));
        mB = fmaxf(mB, __shfl_xor_sync(0xffffffffu, mB, 2));

        float mnA = fmaxf(mrA, mA);
        float mnB = fmaxf(mrB, mB);
        float cA = __expf(mrA - mnA);
        float cB = __expf(mrB - mnB);
        mrA = mnA; mrB = mnB;

        float sumA = 0.0f, sumB = 0.0f;
#pragma unroll
        for (int nt = 0; nt < 8; nt++) {
            s[nt][0] = __expf(s[nt][0] - mnA);
            s[nt][1] = __expf(s[nt][1] - mnA);
            s[nt][2] = __expf(s[nt][2] - mnB);
            s[nt][3] = __expf(s[nt][3] - mnB);
            sumA += s[nt][0] + s[nt][1];
            sumB += s[nt][2] + s[nt][3];
        }
        sumA += __shfl_xor_sync(0xffffffffu, sumA, 1);
        sumA += __shfl_xor_sync(0xffffffffu, sumA, 2);
        sumB += __shfl_xor_sync(0xffffffffu, sumB, 1);
        sumB += __shfl_xor_sync(0xffffffffu, sumB, 2);
        lA = lA * cA + sumA;
        lB = lB * cB + sumB;
#pragma unroll
        for (int nt = 0; nt < 8; nt++) {
            o[nt][0] *= cA;
            o[nt][1] *= cA;
            o[nt][2] *= cB;
            o[nt][3] *= cB;
        }

#pragma unroll
        for (int ks = 0; ks < 4; ks++) {
            uint32_t pa[4];
            pa[0] = f2h2(s[2 * ks][0],     s[2 * ks][1]);
            pa[1] = f2h2(s[2 * ks][2],     s[2 * ks][3]);
            pa[2] = f2h2(s[2 * ks + 1][0], s[2 * ks + 1][1]);
            pa[3] = f2h2(s[2 * ks + 1][2], s[2 * ks + 1][3]);
#pragma unroll
            for (int p = 0; p < 4; p++) {
                uint32_t bv[4];
                int rr = ks * 16 + (lane & 7) + (((lane >> 3) & 1) << 3);
                int cc = 2 * p + (lane >> 4);
                ldsm4t(bv, vT + rr * 128 + ((cc ^ (rr & 7)) * 16));
                mma_f16(o[2 * p],     pa, &bv[0]);
                mma_f16(o[2 * p + 1], pa, &bv[2]);
            }
        }
    }
#undef KV_ISSUE

    float iA = 1.0f / lA;
    float iB = 1.0f / lB;
    int rA = q0 + w * 16 + lr;
    int rB = rA + 8;
    size_t baseA = ((size_t)bb * S_ + rA) * C_ + h * D_;
    size_t baseB = ((size_t)bb * S_ + rB) * C_ + h * D_;
#pragma unroll
    for (int nt = 0; nt < 8; nt++) {
        int c = nt * 8 + 2 * lc;
        *reinterpret_cast<__half2*>(&g_x[baseA + c]) =
            __floats2half2_rn(o[nt][0] * iA, o[nt][1] * iA);
        *reinterpret_cast<__half2*>(&g_x[baseB + c]) =
            __floats2half2_rn(o[nt][2] * iB, o[nt][3] * iB);
    }
}

// ---------------------------------------------------------------------------
extern "C" void kernel_launch(void* const* d_in, const int* in_sizes, int n_in,
                              void* d_out, int out_size)
{
    const float* query = (const float*)d_in[0];
    const float* key   = (const float*)d_in[1];
    const int*   qpos  = (const int*)d_in[2];
    const int*   kpos  = (const int*)d_in[3];
    const float* Wq    = (const float*)d_in[4];
    const float* bq    = (const float*)d_in[5];
    const float* Wk    = (const float*)d_in[6];
    const float* Wv    = (const float*)d_in[7];
    const float* bv    = (const float*)d_in[8];
    const float* Wo    = (const float*)d_in[9];
    const float* bo    = (const float*)d_in[10];
    float* out = (float*)d_out;

    const int gemm_smem = 4 * 8192 * 2;   // 64 KB (A 32KB + B 32KB)
    cudaFuncSetAttribute(gemm_qkv, cudaFuncAttributeMaxDynamicSharedMemorySize, gemm_smem);
    cudaFuncSetAttribute(gemm_o,   cudaFuncAttributeMaxDynamicSharedMemorySize, gemm_smem);
    const int flash_smem = 32768 * 2;     // 64 KB
    cudaFuncSetAttribute(flash_f16, cudaFuncAttributeMaxDynamicSharedMemorySize, flash_smem);

    // 1. fp32 -> fp16 inputs/weights
    cvt_kernel<<<12288, 256>>>(query, key, Wq, Wk, Wv, Wo);

    // 2. Q/K/V projections in ONE launch (grid.z selects) -> [B,H,S,D] fp16
    gemm_qkv<<<dim3(C_ / 128, GM / 128, 3), 256, gemm_smem>>>(bq, bv);

    // 3. RoPE in place on q and k
    rope_kernel<<<2048, 256>>>(qpos, kpos);

    // 4. attention -> g_x [B,N,C] fp16
    flash_f16<<<dim3(S_ / 128, H_, B_), 256, flash_smem>>>();

    // 5. output projection + bias + residual -> d_out (fp32)
    gemm_o<<<dim3(C_ / 128, GM / 128), 256, gemm_smem>>>(bo, query, out);
}

// round 8
// speedup vs baseline: 7.2778x; 1.0794x over previous
#include <cuda_runtime.h>
#include <cuda_fp16.h>
#include <stdint.h>
#include <math.h>

// Problem constants (fixed shapes from setup_inputs)
#define B_ 2
#define S_ 2048      // N == M == 2048
#define C_ 1024
#define H_ 16
#define D_ 64
#define GM (B_*S_)   // 4096 rows for the projection GEMMs

// Q pre-scale: D^-0.5 * log2(e), folded into the Q projection epilogue so
// flash softmax runs in exp2 domain with zero per-element scaling.
#define QSCALE 0.1803368801111204f

// fp16 scratch (device globals; no allocation allowed)
__device__ __half g_hA[GM*C_];       // fp16 query
__device__ __half g_hK[GM*C_];       // fp16 key
__device__ __half g_hWq[C_*C_];
__device__ __half g_hWk[C_*C_];
__device__ __half g_hWv[C_*C_];
__device__ __half g_hWo[C_*C_];
__device__ __half g_q[B_*H_*S_*D_];  // [B,H,S,D] fp16 (pre-scaled by QSCALE)
__device__ __half g_k[B_*H_*S_*D_];
__device__ __half g_v[B_*H_*S_*D_];
__device__ __half g_x[B_*S_*C_];     // attention output [B,N,C] fp16

__device__ __forceinline__ uint32_t f2h2(float lo, float hi) {
    __half2 h = __floats2half2_rn(lo, hi);
    return *reinterpret_cast<uint32_t*>(&h);
}
__device__ __forceinline__ float ex2(float x) {
    float y;
    asm("ex2.approx.ftz.f32 %0, %1;" : "=f"(y) : "f"(x));
    return y;
}
__device__ __forceinline__ void mma_f16(float* c, const uint32_t* a, const uint32_t* b) {
    asm volatile(
        "mma.sync.aligned.m16n8k16.row.col.f32.f16.f16.f32 "
        "{%0,%1,%2,%3}, {%4,%5,%6,%7}, {%8,%9}, {%0,%1,%2,%3};"
        : "+f"(c[0]), "+f"(c[1]), "+f"(c[2]), "+f"(c[3])
        : "r"(a[0]), "r"(a[1]), "r"(a[2]), "r"(a[3]), "r"(b[0]), "r"(b[1]));
}
__device__ __forceinline__ void ldsm4(uint32_t* r, uint32_t a) {
    asm volatile("ldmatrix.sync.aligned.m8n8.x4.shared.b16 {%0,%1,%2,%3}, [%4];"
        : "=r"(r[0]), "=r"(r[1]), "=r"(r[2]), "=r"(r[3]) : "r"(a));
}
__device__ __forceinline__ void ldsm4t(uint32_t* r, uint32_t a) {
    asm volatile("ldmatrix.sync.aligned.m8n8.x4.trans.shared.b16 {%0,%1,%2,%3}, [%4];"
        : "=r"(r[0]), "=r"(r[1]), "=r"(r[2]), "=r"(r[3]) : "r"(a));
}
__device__ __forceinline__ void cpa16(uint32_t saddr, const void* g) {
    asm volatile("cp.async.cg.shared.global [%0], [%1], 16;\n" :: "r"(saddr), "l"(g));
}
#define CP_COMMIT() asm volatile("cp.async.commit_group;\n")
#define CP_WAIT2()  asm volatile("cp.async.wait_group 2;\n")
#define CP_WAIT1()  asm volatile("cp.async.wait_group 1;\n")
#define CP_WAIT0()  asm volatile("cp.async.wait_group 0;\n")

// ---------------------------------------------------------------------------
// One-shot fp32 -> fp16 conversion of query, key, Wq, Wk, Wv, Wo.
// ---------------------------------------------------------------------------
__global__ void cvt_kernel(const float* __restrict__ q, const float* __restrict__ k,
                           const float* __restrict__ wq, const float* __restrict__ wk,
                           const float* __restrict__ wv, const float* __restrict__ wo)
{
    int i = blockIdx.x * blockDim.x + threadIdx.x;   // float4 index
    const float* src; __half* dst; int off;
    if      (i < 1048576) { src = q;  dst = g_hA;  off = i; }
    else if (i < 2097152) { src = k;  dst = g_hK;  off = i - 1048576; }
    else if (i < 2359296) { src = wq; dst = g_hWq; off = i - 2097152; }
    else if (i < 2621440) { src = wk; dst = g_hWk; off = i - 2359296; }
    else if (i < 2883584) { src = wv; dst = g_hWv; off = i - 2621440; }
    else                  { src = wo; dst = g_hWo; off = i - 2883584; }
    float4 v = reinterpret_cast<const float4*>(src)[off];
    __half2* d2 = reinterpret_cast<__half2*>(dst) + off * 2;
    d2[0] = __floats2half2_rn(v.x, v.y);
    d2[1] = __floats2half2_rn(v.z, v.w);
}

// ---------------------------------------------------------------------------
// FP16 GEMM body (R7, proven): 128x128 tile, BK=32, 8 warps, 4-stage cp.async.
// oscale multiplies (acc+bias) on the fp16 [B,H,S,D] path (QSCALE for Q).
// ---------------------------------------------------------------------------
__device__ __forceinline__
void gemm_body(const __half* __restrict__ A, const __half* __restrict__ W,
               const float* __restrict__ bias, const float* __restrict__ resid,
               __half* __restrict__ outh, float* __restrict__ outf, float oscale)
{
    extern __shared__ __half gsm[];
    const uint32_t sAb = (uint32_t)__cvta_generic_to_shared(gsm);            // 4 x 8KB
    const uint32_t sBb = sAb + 32768;                                        // 4 x 8KB

    const int tid = threadIdx.x;
    const int lane = tid & 31;
    const int w = tid >> 5;
    const int wm = (w & 1) * 64;
    const int wn = (w >> 1) * 32;
    const int lr = lane >> 2;
    const int lc = lane & 3;
    const int m0 = blockIdx.y * 128;
    const int n0 = blockIdx.x * 128;

    float acc[4][4][4];
#pragma unroll
    for (int mt = 0; mt < 4; mt++)
#pragma unroll
        for (int nt = 0; nt < 4; nt++)
#pragma unroll
            for (int j = 0; j < 4; j++) acc[mt][nt][j] = 0.0f;

#define G_ISSUE(st, k0)                                                        \
    {                                                                          \
        _Pragma("unroll")                                                      \
        for (int i_ = 0; i_ < 2; i_++) {                                       \
            int l = tid + i_ * 256;                                            \
            int row = l >> 2;                                                  \
            int c = l & 3;                                                     \
            int cs = c ^ ((row >> 1) & 3);                                     \
            cpa16(sAb + (st) * 8192 + row * 64 + cs * 16,                      \
                  A + (size_t)(m0 + row) * C_ + (k0) + c * 8);                 \
            cpa16(sBb + (st) * 8192 + row * 64 + cs * 16,                      \
                  W + (size_t)(n0 + row) * C_ + (k0) + c * 8);                 \
        }                                                                      \
    }

    G_ISSUE(0, 0);   CP_COMMIT();
    G_ISSUE(1, 32);  CP_COMMIT();
    G_ISSUE(2, 64);  CP_COMMIT();

    const int NIT = C_ / 32;   // 32
    for (int it = 0; it < NIT; it++) {
        CP_WAIT2();
        __syncthreads();
        if (it + 3 < NIT) { int st = (it + 3) & 3; G_ISSUE(st, (it + 3) * 32); }
        CP_COMMIT();

        const int cur = it & 3;
        const uint32_t aB = sAb + cur * 8192;
        const uint32_t bB = sBb + cur * 8192;
#pragma unroll
        for (int ks = 0; ks < 2; ks++) {
            uint32_t bf[2][4];
#pragma unroll
            for (int p = 0; p < 2; p++) {
                int rr = wn + p * 16 + (lane & 7) + ((lane >> 4) << 3);
                int cc = 2 * ks + ((lane >> 3) & 1);
                ldsm4(bf[p], bB + rr * 64 + ((cc ^ ((rr >> 1) & 3)) * 16));
            }
#pragma unroll
            for (int mt = 0; mt < 4; mt++) {
                uint32_t af[4];
                int rr = wm + mt * 16 + (lane & 15);
                int cc = 2 * ks + (lane >> 4);
                ldsm4(af, aB + rr * 64 + ((cc ^ ((rr >> 1) & 3)) * 16));
                mma_f16(acc[mt][0], af, &bf[0][0]);
                mma_f16(acc[mt][1], af, &bf[0][2]);
                mma_f16(acc[mt][2], af, &bf[1][0]);
                mma_f16(acc[mt][3], af, &bf[1][2]);
            }
        }
    }
#undef G_ISSUE

#pragma unroll
    for (int mt = 0; mt < 4; mt++) {
#pragma unroll
        for (int half = 0; half < 2; half++) {
            int r = m0 + wm + mt * 16 + lr + half * 8;
            int bb = r >> 11;
            int s = r & (S_ - 1);
#pragma unroll
            for (int nt = 0; nt < 4; nt++) {
                int c = n0 + wn + nt * 8 + 2 * lc;
                float v0 = acc[mt][nt][half * 2 + 0];
                float v1 = acc[mt][nt][half * 2 + 1];
                if (bias) { v0 += bias[c]; v1 += bias[c + 1]; }
                if (outh) {
                    v0 *= oscale; v1 *= oscale;
                    int h = c >> 6;
                    int d = c & 63;
                    *reinterpret_cast<__half2*>(
                        &outh[(((size_t)(bb * H_ + h)) * S_ + s) * D_ + d]) =
                        __floats2half2_rn(v0, v1);
                } else {
                    v0 += resid[(size_t)r * C_ + c];
                    v1 += resid[(size_t)r * C_ + c + 1];
                    outf[(size_t)r * C_ + c]     = v0;
                    outf[(size_t)r * C_ + c + 1] = v1;
                }
            }
        }
    }
}

// Merged Q/K/V projection: grid.z selects (source, weight, bias, dest, scale).
__global__ __launch_bounds__(256, 2)
void gemm_qkv(const float* __restrict__ bq, const float* __restrict__ bv)
{
    const __half* A; const __half* W; const float* bias; __half* outh; float sc;
    if (blockIdx.z == 0)      { A = g_hA; W = g_hWq; bias = bq;      outh = g_q; sc = QSCALE; }
    else if (blockIdx.z == 1) { A = g_hK; W = g_hWk; bias = nullptr; outh = g_k; sc = 1.0f; }
    else                      { A = g_hK; W = g_hWv; bias = bv;      outh = g_v; sc = 1.0f; }
    gemm_body(A, W, bias, nullptr, outh, nullptr, sc);
}

// Output projection: fp32 out + bias + residual.
__global__ __launch_bounds__(256, 2)
void gemm_o(const float* __restrict__ bo, const float* __restrict__ resid,
            float* __restrict__ out)
{
    gemm_body(g_x, g_hWo, bo, resid, nullptr, out, 1.0f);
}

// ---------------------------------------------------------------------------
// RoPE in place on fp16 g_q / g_k ([B,H,S,D]). 4 threads per row, uint4 I/O.
// (Q is pre-scaled by QSCALE; rotation commutes with scalar scale.)
// ---------------------------------------------------------------------------
__global__ void rope_kernel(const int* __restrict__ qpos, const int* __restrict__ kpos)
{
    int t = blockIdx.x * blockDim.x + threadIdx.x;   // 524288 threads
    int q = t & 3;
    int row = t >> 2;                                // 0..131071
    __half* buf;
    const int* pos;
    int r = row;
    if (row < 65536) { buf = g_q; pos = qpos; }
    else             { r = row - 65536; buf = g_k; pos = kpos; }
    int s  = r & (S_ - 1);
    int bb = r >> 15;

    int p = pos[bb * S_ + s];
    float fp = (float)p;

    size_t base = (size_t)r * D_ + 8 * q;
    uint4 X = *reinterpret_cast<const uint4*>(&buf[base]);
    uint4 Y = *reinterpret_cast<const uint4*>(&buf[base + 32]);
    const __half2* xh = reinterpret_cast<const __half2*>(&X);
    const __half2* yh = reinterpret_cast<const __half2*>(&Y);
    uint4 Xo, Yo;
    __half2* xo = reinterpret_cast<__half2*>(&Xo);
    __half2* yo = reinterpret_cast<__half2*>(&Yo);

#pragma unroll
    for (int i = 0; i < 4; i++) {
        int j0 = 8 * q + 2 * i;
        float invf0 = exp2f(-(float)j0 * (13.287712379549449f / 32.0f));
        float invf1 = exp2f(-(float)(j0 + 1) * (13.287712379549449f / 32.0f));
        float sn0, cs0, sn1, cs1;
        sincosf(fp * invf0, &sn0, &cs0);
        sincosf(fp * invf1, &sn1, &cs1);
        float x1a = __low2float(xh[i]), x1b = __high2float(xh[i]);
        float x2a = __low2float(yh[i]), x2b = __high2float(yh[i]);
        xo[i] = __floats2half2_rn(x1a * cs0 - x2a * sn0, x1b * cs1 - x2b * sn1);
        yo[i] = __floats2half2_rn(x2a * cs0 + x1a * sn0, x2b * cs1 + x1b * sn1);
    }
    *reinterpret_cast<uint4*>(&buf[base])      = Xo;
    *reinterpret_cast<uint4*>(&buf[base + 32]) = Yo;
}

// ---------------------------------------------------------------------------
// Flash attention, software-pipelined: QK_{i+1} -> PV_i -> softmax_{i+1}.
// Block = (b, h, 128 q rows); 8 warps, warp w owns q rows [16w, 16w+16).
// Dynamic smem 80 KB: Q [128][64] @0, K 4 stages [64][64] @16KB, V @48KB.
// exp2-domain softmax (Q pre-scaled by QSCALE); P packed into registers.
// ---------------------------------------------------------------------------
__global__ __launch_bounds__(256, 2)
void flash_f16()
{
    extern __shared__ __half fsm[];
    const uint32_t smb = (uint32_t)__cvta_generic_to_shared(fsm);
    const uint32_t qB = smb;
    const uint32_t kB0 = smb + 16384;
    const uint32_t vB0 = smb + 49152;

    const int tid = threadIdx.x;
    const int lane = tid & 31;
    const int w = tid >> 5;
    const int lr = lane >> 2;
    const int lc = lane & 3;

    const int q0 = blockIdx.x * 128;
    const int h = blockIdx.y;
    const int bb = blockIdx.z;

    const __half* qb = g_q + (size_t)(bb * H_ + h) * S_ * D_;
    const __half* kb = g_k + (size_t)(bb * H_ + h) * S_ * D_;
    const __half* vb = g_v + (size_t)(bb * H_ + h) * S_ * D_;

#define KV_ISSUE(st, kt)                                                       \
    {                                                                          \
        _Pragma("unroll")                                                      \
        for (int i_ = 0; i_ < 2; i_++) {                                       \
            int l = tid + i_ * 256;                                            \
            int row = l >> 3;                                                  \
            int c = l & 7;                                                     \
            int cs = c ^ (row & 7);                                            \
            cpa16(kB0 + (st) * 8192 + row * 128 + cs * 16,                     \
                  kb + (size_t)((kt) + row) * D_ + c * 8);                     \
            cpa16(vB0 + (st) * 8192 + row * 128 + cs * 16,                     \
                  vb + (size_t)((kt) + row) * D_ + c * 8);                     \
        }                                                                      \
    }

    // ---- Prologue: G0 = Q + KV0, G1 = KV1, G2 = KV2 ----
#pragma unroll
    for (int i_ = 0; i_ < 4; i_++) {
        int l = tid + i_ * 256;
        int row = l >> 3;
        int c = l & 7;
        int cs = c ^ (row & 7);
        cpa16(qB + row * 128 + cs * 16, qb + (size_t)(q0 + row) * D_ + c * 8);
    }
    KV_ISSUE(0, 0);   CP_COMMIT();
    KV_ISSUE(1, 64);  CP_COMMIT();
    KV_ISSUE(2, 128); CP_COMMIT();

    CP_WAIT2();            // G0 complete (Q + KV stage 0)
    __syncthreads();

    uint32_t qa[4][4];
#pragma unroll
    for (int ks = 0; ks < 4; ks++) {
        int rr = w * 16 + (lane & 15);
        int cc = 2 * ks + (lane >> 4);
        ldsm4(qa[ks], qB + rr * 128 + ((cc ^ (rr & 7)) * 16));
    }

    float o[8][4];
#pragma unroll
    for (int nt = 0; nt < 8; nt++)
#pragma unroll
        for (int j = 0; j < 4; j++) o[nt][j] = 0.0f;
    float mrA = -1e30f, mrB = -1e30f, lA = 0.0f, lB = 0.0f;
    float s[8][4];
    uint32_t pa[16];

#define QK_TILE(tile)                                                          \
    {                                                                          \
        const uint32_t kT = kB0 + ((tile) & 3) * 8192;                         \
        _Pragma("unroll")                                                      \
        for (int nt = 0; nt < 8; nt++)                                         \
            { s[nt][0]=0.f; s[nt][1]=0.f; s[nt][2]=0.f; s[nt][3]=0.f; }        \
        _Pragma("unroll")                                                      \
        for (int ks = 0; ks < 4; ks++) {                                       \
            _Pragma("unroll")                                                  \
            for (int p = 0; p < 4; p++) {                                      \
                uint32_t bf[4];                                                \
                int rr = p * 16 + (lane & 7) + ((lane >> 4) << 3);             \
                int cc = 2 * ks + ((lane >> 3) & 1);                           \
                ldsm4(bf, kT + rr * 128 + ((cc ^ (rr & 7)) * 16));             \
                mma_f16(s[2 * p],     qa[ks], &bf[0]);                         \
                mma_f16(s[2 * p + 1], qa[ks], &bf[2]);                         \
            }                                                                  \
        }                                                                      \
    }

    // exp2-domain online softmax; packs P into pa[], rescales o and l
#define SOFTMAX()                                                              \
    {                                                                          \
        float mA = -1e30f, mB = -1e30f;                                        \
        _Pragma("unroll")                                                      \
        for (int nt = 0; nt < 8; nt++) {                                       \
            mA = fmaxf(mA, fmaxf(s[nt][0], s[nt][1]));                         \
            mB = fmaxf(mB, fmaxf(s[nt][2], s[nt][3]));                         \
        }                                                                      \
        mA = fmaxf(mA, __shfl_xor_sync(0xffffffffu, mA, 1));                   \
        mA = fmaxf(mA, __shfl_xor_sync(0xffffffffu, mA, 2));                   \
        mB = fmaxf(mB, __shfl_xor_sync(0xffffffffu, mB, 1));                   \
        mB = fmaxf(mB, __shfl_xor_sync(0xffffffffu, mB, 2));                   \
        float mnA = fmaxf(mrA, mA);                                            \
        float mnB = fmaxf(mrB, mB);                                            \
        float cA = ex2(mrA - mnA);                                             \
        float cB = ex2(mrB - mnB);                                             \
        mrA = mnA; mrB = mnB;                                                  \
        float sumA = 0.0f, sumB = 0.0f;                                        \
        _Pragma("unroll")                                                      \
        for (int nt = 0; nt < 8; nt++) {                                       \
            float p0 = ex2(s[nt][0] - mnA);                                    \
            float p1 = ex2(s[nt][1] - mnA);                                    \
            float p2 = ex2(s[nt][2] - mnB);                                    \
            float p3 = ex2(s[nt][3] - mnB);                                    \
            sumA += p0 + p1; sumB += p2 + p3;                                  \
            s[nt][0] = p0; s[nt][1] = p1; s[nt][2] = p2; s[nt][3] = p3;        \
        }                                                                      \
        sumA += __shfl_xor_sync(0xffffffffu, sumA, 1);                         \
        sumA += __shfl_xor_sync(0xffffffffu, sumA, 2);                         \
        sumB += __shfl_xor_sync(0xffffffffu, sumB, 1);                         \
        sumB += __shfl_xor_sync(0xffffffffu, sumB, 2);                         \
        lA = lA * cA + sumA;                                                   \
        lB = lB * cB + sumB;                                                   \
        _Pragma("unroll")                                                      \
        for (int nt = 0; nt < 8; nt++) {                                       \
            o[nt][0] *= cA; o[nt][1] *= cA; o[nt][2] *= cB; o[nt][3] *= cB;    \
        }                                                                      \
        _Pragma("unroll")                                                      \
        for (int ks = 0; ks < 4; ks++) {                                       \
            pa[4 * ks + 0] = f2h2(s[2 * ks][0],     s[2 * ks][1]);             \
            pa[4 * ks + 1] = f2h2(s[2 * ks][2],     s[2 * ks][3]);             \
            pa[4 * ks + 2] = f2h2(s[2 * ks + 1][0], s[2 * ks + 1][1]);         \
            pa[4 * ks + 3] = f2h2(s[2 * ks + 1][2], s[2 * ks + 1][3]);         \
        }                                                                      \
    }

#define PV_TILE(tile)                                                          \
    {                                                                          \
        const uint32_t vT = vB0 + ((tile) & 3) * 8192;                         \
        _Pragma("unroll")                                                      \
        for (int ks = 0; ks < 4; ks++) {                                       \
            _Pragma("unroll")                                                  \
            for (int p = 0; p < 4; p++) {                                      \
                uint32_t bv[4];                                                \
                int rr = ks * 16 + (lane & 7) + (((lane >> 3) & 1) << 3);      \
                int cc = 2 * p + (lane >> 4);                                  \
                ldsm4t(bv, vT + rr * 128 + ((cc ^ (rr & 7)) * 16));            \
                mma_f16(o[2 * p],     &pa[4 * ks], &bv[0]);                    \
                mma_f16(o[2 * p + 1], &pa[4 * ks], &bv[2]);                    \
            }                                                                  \
        }                                                                      \
    }

    // Peel: QK_0 + softmax_0
    QK_TILE(0);
    SOFTMAX();

    const int NITER = S_ / 64;    // 32
    for (int i = 0; i < NITER; i++) {
        if (i + 1 < NITER) {
            CP_WAIT1();                 // G_{i+1} complete
            __syncthreads();            // all warps done reading stage (i-1)&3
            if (i + 3 < NITER) KV_ISSUE((i + 3) & 3, (i + 3) * 64);
            CP_COMMIT();                // uniform commit keeps wait count exact
            QK_TILE(i + 1);             // independent of pa/o -> overlaps PV_i
        }
        PV_TILE(i);
        if (i + 1 < NITER) SOFTMAX();   // rescale o AFTER PV_i, produce pa_{i+1}
    }
#undef KV_ISSUE
#undef QK_TILE
#undef SOFTMAX
#undef PV_TILE

    float iA = 1.0f / lA;
    float iB = 1.0f / lB;
    int rA = q0 + w * 16 + lr;
    int rB = rA + 8;
    size_t baseA = ((size_t)bb * S_ + rA) * C_ + h * D_;
    size_t baseB = ((size_t)bb * S_ + rB) * C_ + h * D_;
#pragma unroll
    for (int nt = 0; nt < 8; nt++) {
        int c = nt * 8 + 2 * lc;
        *reinterpret_cast<__half2*>(&g_x[baseA + c]) =
            __floats2half2_rn(o[nt][0] * iA, o[nt][1] * iA);
        *reinterpret_cast<__half2*>(&g_x[baseB + c]) =
            __floats2half2_rn(o[nt][2] * iB, o[nt][3] * iB);
    }
}

// ---------------------------------------------------------------------------
extern "C" void kernel_launch(void* const* d_in, const int* in_sizes, int n_in,
                              void* d_out, int out_size)
{
    const float* query = (const float*)d_in[0];
    const float* key   = (const float*)d_in[1];
    const int*   qpos  = (const int*)d_in[2];
    const int*   kpos  = (const int*)d_in[3];
    const float* Wq    = (const float*)d_in[4];
    const float* bq    = (const float*)d_in[5];
    const float* Wk    = (const float*)d_in[6];
    const float* Wv    = (const float*)d_in[7];
    const float* bv    = (const float*)d_in[8];
    const float* Wo    = (const float*)d_in[9];
    const float* bo    = (const float*)d_in[10];
    float* out = (float*)d_out;

    const int gemm_smem = 4 * 8192 * 2;   // 64 KB
    cudaFuncSetAttribute(gemm_qkv, cudaFuncAttributeMaxDynamicSharedMemorySize, gemm_smem);
    cudaFuncSetAttribute(gemm_o,   cudaFuncAttributeMaxDynamicSharedMemorySize, gemm_smem);
    const int flash_smem = 16384 + 4 * 8192 * 2;   // 80 KB
    cudaFuncSetAttribute(flash_f16, cudaFuncAttributeMaxDynamicSharedMemorySize, flash_smem);

    // 1. fp32 -> fp16 inputs/weights
    cvt_kernel<<<12288, 256>>>(query, key, Wq, Wk, Wv, Wo);

    // 2. Q/K/V projections in ONE launch (grid.z selects) -> [B,H,S,D] fp16
    gemm_qkv<<<dim3(C_ / 128, GM / 128, 3), 256, gemm_smem>>>(bq, bv);

    // 3. RoPE in place on q and k
    rope_kernel<<<2048, 256>>>(qpos, kpos);

    // 4. attention -> g_x [B,N,C] fp16
    flash_f16<<<dim3(S_ / 128, H_, B_), 256, flash_smem>>>();

    // 5. output projection + bias + residual -> d_out (fp32)
    gemm_o<<<dim3(C_ / 128, GM / 128), 256, gemm_smem>>>(bo, query, out);
}